// round 1
// baseline (speedup 1.0000x reference)
#include <cuda_runtime.h>
#include <math.h>

#define BATCH 65536
#define F     512
#define HID   256
#define NCLS  10

// ---------------- scratch (static __device__, no allocations) ----------------
__device__ float  g_x4[(size_t)BATCH * F];   // 128 MB activation scratch
__device__ float  g_fsum[NCLS * F];          // per-class column sums of x4
__device__ int    g_counts[NCLS];
__device__ double g_s2, g_ce, g_l1, g_acc;

// ---------------- init ----------------
__global__ void init_kernel() {
    int i = blockIdx.x * blockDim.x + threadIdx.x;
    if (i < NCLS * F) g_fsum[i] = 0.f;
    if (i < NCLS)     g_counts[i] = 0;
    if (i == 0) { g_s2 = 0.0; g_ce = 0.0; g_l1 = 0.0; g_acc = 0.0; }
}

// ---------------- histogram of y ----------------
__global__ void hist_kernel(const int* __restrict__ y) {
    __shared__ int h[NCLS];
    if (threadIdx.x < NCLS) h[threadIdx.x] = 0;
    __syncthreads();
    int i = blockIdx.x * blockDim.x + threadIdx.x;
    int stride = gridDim.x * blockDim.x;
    for (; i < BATCH; i += stride) atomicAdd(&h[y[i]], 1);
    __syncthreads();
    if (threadIdx.x < NCLS) atomicAdd(&g_counts[threadIdx.x], h[threadIdx.x]);
}

// ---------------- fused gate: x4 = x + (1+sigmoid(x@fc0))*relu(x@fc1) --------
// Also accumulates sum(x4^2) and per-class column sums of x4.
#define BM 128
#define BN 64
#define BK 32

__global__ __launch_bounds__(256) void gate_kernel(
    const float* __restrict__ x, const float* __restrict__ fc0,
    const float* __restrict__ fc1, const int* __restrict__ y)
{
    __shared__ float As[BM][BK];      // 16 KB
    __shared__ float B0s[BK][BN];     // 8 KB
    __shared__ float B1s[BK][BN];     // 8 KB
    __shared__ float csum[NCLS][BN];  // 2.5 KB
    __shared__ float red[8];

    const int tid = threadIdx.x;
    const int tx = tid & 15;   // col group (0..15), 4 cols each
    const int ty = tid >> 4;   // row group (0..15), 8 rows each
    const int rowBase = blockIdx.y * BM;
    const int colBase = blockIdx.x * BN;

    float acc0[8][4];
    float acc1[8][4];
#pragma unroll
    for (int i = 0; i < 8; i++)
#pragma unroll
        for (int j = 0; j < 4; j++) { acc0[i][j] = 0.f; acc1[i][j] = 0.f; }

    for (int kb = 0; kb < F; kb += BK) {
        // load x tile [128][32]: 1024 float4, 4 per thread
#pragma unroll
        for (int l = 0; l < 4; l++) {
            int idx = tid + l * 256;
            int r = idx >> 3, k4 = idx & 7;
            *(float4*)&As[r][k4 * 4] =
                *(const float4*)&x[(size_t)(rowBase + r) * F + kb + k4 * 4];
        }
        // load fc tiles [32][64]: 512 float4 each, 2 per thread
#pragma unroll
        for (int l = 0; l < 2; l++) {
            int idx = tid + l * 256;
            int k = idx >> 4, c4 = idx & 15;
            *(float4*)&B0s[k][c4 * 4] =
                *(const float4*)&fc0[(size_t)(kb + k) * F + colBase + c4 * 4];
            *(float4*)&B1s[k][c4 * 4] =
                *(const float4*)&fc1[(size_t)(kb + k) * F + colBase + c4 * 4];
        }
        __syncthreads();
#pragma unroll 8
        for (int kk = 0; kk < BK; kk++) {
            float a[8];
#pragma unroll
            for (int i = 0; i < 8; i++) a[i] = As[ty * 8 + i][kk];
            float4 b0 = *(float4*)&B0s[kk][tx * 4];
            float4 b1 = *(float4*)&B1s[kk][tx * 4];
#pragma unroll
            for (int i = 0; i < 8; i++) {
                acc0[i][0] += a[i] * b0.x; acc0[i][1] += a[i] * b0.y;
                acc0[i][2] += a[i] * b0.z; acc0[i][3] += a[i] * b0.w;
                acc1[i][0] += a[i] * b1.x; acc1[i][1] += a[i] * b1.y;
                acc1[i][2] += a[i] * b1.z; acc1[i][3] += a[i] * b1.w;
            }
        }
        __syncthreads();
    }

    // epilogue: x4, s2, class sums
    for (int i2 = tid; i2 < NCLS * BN; i2 += 256) ((float*)csum)[i2] = 0.f;
    __syncthreads();

    float s2loc = 0.f;
#pragma unroll
    for (int i = 0; i < 8; i++) {
        int row = rowBase + ty * 8 + i;
        int yr = y[row];
        float4 xv = *(const float4*)&x[(size_t)row * F + colBase + tx * 4];
        float4 o;
        {
            float g0 = 1.f + 1.f / (1.f + expf(-acc0[i][0]));
            float g1 = 1.f + 1.f / (1.f + expf(-acc0[i][1]));
            float g2 = 1.f + 1.f / (1.f + expf(-acc0[i][2]));
            float g3 = 1.f + 1.f / (1.f + expf(-acc0[i][3]));
            o.x = xv.x + g0 * fmaxf(acc1[i][0], 0.f);
            o.y = xv.y + g1 * fmaxf(acc1[i][1], 0.f);
            o.z = xv.z + g2 * fmaxf(acc1[i][2], 0.f);
            o.w = xv.w + g3 * fmaxf(acc1[i][3], 0.f);
        }
        *(float4*)&g_x4[(size_t)row * F + colBase + tx * 4] = o;
        s2loc += o.x * o.x + o.y * o.y + o.z * o.z + o.w * o.w;
        atomicAdd(&csum[yr][tx * 4 + 0], o.x);
        atomicAdd(&csum[yr][tx * 4 + 1], o.y);
        atomicAdd(&csum[yr][tx * 4 + 2], o.z);
        atomicAdd(&csum[yr][tx * 4 + 3], o.w);
    }
    __syncthreads();

    for (int i2 = tid; i2 < NCLS * BN; i2 += 256) {
        float v = ((float*)csum)[i2];
        if (v != 0.f) {
            int c = i2 / BN, col = i2 % BN;
            atomicAdd(&g_fsum[c * F + colBase + col], v);
        }
    }

#pragma unroll
    for (int o = 16; o; o >>= 1) s2loc += __shfl_xor_sync(0xffffffffu, s2loc, o);
    if ((tid & 31) == 0) red[tid >> 5] = s2loc;
    __syncthreads();
    if (tid == 0) {
        float t = 0.f;
        for (int i = 0; i < 8; i++) t += red[i];
        atomicAdd(&g_s2, (double)t);
    }
}

// ---------------- L1 penalty sums ----------------
__global__ void l1_kernel(const float* __restrict__ fc0, const float* __restrict__ fc1,
                          const float* __restrict__ w, const float* __restrict__ w1)
{
    float s = 0.f;
    int i0 = blockIdx.x * blockDim.x + threadIdx.x;
    int stride = gridDim.x * blockDim.x;
    for (int k = i0; k < F * F; k += stride) s += fabsf(fc0[k]) + fabsf(fc1[k]);
    for (int k = i0; k < F * HID; k += stride) s += fabsf(w[k]);
    for (int k = i0; k < HID * NCLS; k += stride) s += fabsf(w1[k]);
#pragma unroll
    for (int o = 16; o; o >>= 1) s += __shfl_xor_sync(0xffffffffu, s, o);
    __shared__ float red[8];
    if ((threadIdx.x & 31) == 0) red[threadIdx.x >> 5] = s;
    __syncthreads();
    if (threadIdx.x == 0) {
        float t = 0.f;
        for (int i = 0; i < 8; i++) t += red[i];
        atomicAdd(&g_l1, (double)t);
    }
}

// ---------------- head: logits = relu(x4@w)@w1, CE + acc ----------------
#define BM2 64
#define BK2 16

__global__ __launch_bounds__(256) void head_kernel(
    const float* __restrict__ w, const float* __restrict__ w1,
    const int* __restrict__ y)
{
    __shared__ float As[BM2][BK2];     // 4 KB
    __shared__ float Ws[BK2][HID];     // 16 KB
    __shared__ float w1t[NCLS][HID];   // 10 KB, transposed

    const int tid = threadIdx.x;
    const int tx = tid & 31;   // lane: cols tx*8..tx*8+7
    const int ty = tid >> 5;   // warp: rows ty*8..ty*8+7
    const int rowBase = blockIdx.x * BM2;

    for (int i = tid; i < HID * NCLS; i += 256) {
        int j = i / NCLS, c = i % NCLS;
        w1t[c][j] = w1[i];
    }

    float h[8][8];
#pragma unroll
    for (int i = 0; i < 8; i++)
#pragma unroll
        for (int j = 0; j < 8; j++) h[i][j] = 0.f;

    __syncthreads();
    for (int kb = 0; kb < F; kb += BK2) {
        {   // x4 tile [64][16]: 256 float4, 1 per thread
            int r = tid >> 2, k4 = tid & 3;
            *(float4*)&As[r][k4 * 4] =
                *(const float4*)&g_x4[(size_t)(rowBase + r) * F + kb + k4 * 4];
        }
#pragma unroll
        for (int l = 0; l < 4; l++) {  // w tile [16][256]: 1024 float4
            int idx = tid + l * 256;
            int k = idx >> 6, c4 = idx & 63;
            *(float4*)&Ws[k][c4 * 4] =
                *(const float4*)&w[(size_t)(kb + k) * HID + c4 * 4];
        }
        __syncthreads();
#pragma unroll 8
        for (int kk = 0; kk < BK2; kk++) {
            float a[8];
#pragma unroll
            for (int i = 0; i < 8; i++) a[i] = As[ty * 8 + i][kk];
            float4 b0 = *(float4*)&Ws[kk][tx * 8];
            float4 b1 = *(float4*)&Ws[kk][tx * 8 + 4];
#pragma unroll
            for (int i = 0; i < 8; i++) {
                h[i][0] += a[i] * b0.x; h[i][1] += a[i] * b0.y;
                h[i][2] += a[i] * b0.z; h[i][3] += a[i] * b0.w;
                h[i][4] += a[i] * b1.x; h[i][5] += a[i] * b1.y;
                h[i][6] += a[i] * b1.z; h[i][7] += a[i] * b1.w;
            }
        }
        __syncthreads();
    }

    // relu in place
#pragma unroll
    for (int i = 0; i < 8; i++)
#pragma unroll
        for (int j = 0; j < 8; j++) h[i][j] = fmaxf(h[i][j], 0.f);

    float ce_loc = 0.f, correct_loc = 0.f;
#pragma unroll
    for (int i = 0; i < 8; i++) {
        float l[NCLS];
#pragma unroll
        for (int c = 0; c < NCLS; c++) {
            float4 wa = *(float4*)&w1t[c][tx * 8];
            float4 wb = *(float4*)&w1t[c][tx * 8 + 4];
            l[c] = h[i][0] * wa.x + h[i][1] * wa.y + h[i][2] * wa.z + h[i][3] * wa.w
                 + h[i][4] * wb.x + h[i][5] * wb.y + h[i][6] * wb.z + h[i][7] * wb.w;
        }
#pragma unroll
        for (int c = 0; c < NCLS; c++)
#pragma unroll
            for (int o = 16; o; o >>= 1) l[c] += __shfl_xor_sync(0xffffffffu, l[c], o);

        if (tx == 0) {
            int row = rowBase + ty * 8 + i;
            int yr = y[row];
            float m = l[0]; int bi = 0;
#pragma unroll
            for (int c = 1; c < NCLS; c++) if (l[c] > m) { m = l[c]; bi = c; }
            float se = 0.f;
#pragma unroll
            for (int c = 0; c < NCLS; c++) se += expf(l[c] - m);
            float lse = m + logf(se);
            ce_loc += lse - l[yr];
            if (bi == yr) correct_loc += 1.f;
        }
    }
    if (tx == 0) {
        atomicAdd(&g_ce, (double)ce_loc);
        atomicAdd(&g_acc, (double)correct_loc);
    }
}

// ---------------- finalize ----------------
__global__ void final_kernel(float* __restrict__ out) {
    int tid = threadIdx.x;
    float t = 0.f;
    for (int i = tid; i < NCLS * F; i += 256) {
        int c = i / F;
        int cnt = g_counts[c]; if (cnt < 1) cnt = 1;
        float v = g_fsum[i];
        t += v * v / (float)cnt;
    }
#pragma unroll
    for (int o = 16; o; o >>= 1) t += __shfl_xor_sync(0xffffffffu, t, o);
    __shared__ float red[8];
    if ((tid & 31) == 0) red[tid >> 5] = t;
    __syncthreads();
    if (tid == 0) {
        double tt = 0.0;
        for (int i = 0; i < 8; i++) tt += (double)red[i];
        double var = g_s2 - tt;  // sum ||x4 - mean_y||^2
        double loss = g_ce / (double)BATCH + 1e-4 * g_l1 + 1e-3 * var;
        out[0] = (float)loss;
        out[1] = (float)(g_acc / (double)BATCH);
    }
}

// ---------------- launch ----------------
extern "C" void kernel_launch(void* const* d_in, const int* in_sizes, int n_in,
                              void* d_out, int out_size) {
    const float* x   = (const float*)d_in[0];
    const int*   y   = (const int*)d_in[1];
    const float* fc0 = (const float*)d_in[2];
    const float* fc1 = (const float*)d_in[3];
    const float* w   = (const float*)d_in[4];
    const float* w1  = (const float*)d_in[5];
    float* out = (float*)d_out;

    init_kernel<<<20, 256>>>();
    hist_kernel<<<64, 256>>>(y);
    gate_kernel<<<dim3(F / BN, BATCH / BM), 256>>>(x, fc0, fc1, y);
    l1_kernel<<<256, 256>>>(fc0, fc1, w, w1);
    head_kernel<<<BATCH / BM2, 256>>>(w, w1, y);
    final_kernel<<<1, 256>>>(out);
}

// round 3
// speedup vs baseline: 1.8134x; 1.8134x over previous
#include <cuda_runtime.h>
#include <math.h>
#include <stdint.h>

#define BATCH 65536
#define F     512
#define HID   256
#define NCLS  10

// ---------------- scratch ----------------
__device__ float  g_x4[(size_t)BATCH * F];   // 128 MB
__device__ float  g_fc0T[F * F];
__device__ float  g_fc1T[F * F];
__device__ float  g_wT[HID * F];
__device__ float  g_fsum[NCLS * F];
__device__ int    g_counts[NCLS];
__device__ double g_s2, g_ce, g_l1, g_acc;

// ---------------- helpers ----------------
__device__ __forceinline__ uint32_t f2tf32(float f) {
    uint32_t u;
    asm("cvt.rna.tf32.f32 %0, %1;" : "=r"(u) : "f"(f));
    return u;
}
__device__ __forceinline__ void mma_tf32(float* c, const uint32_t* a, const uint32_t* b) {
    asm volatile("mma.sync.aligned.m16n8k8.row.col.f32.tf32.tf32.f32 "
                 "{%0,%1,%2,%3}, {%4,%5,%6,%7}, {%8,%9}, {%0,%1,%2,%3};"
                 : "+f"(c[0]), "+f"(c[1]), "+f"(c[2]), "+f"(c[3])
                 : "r"(a[0]), "r"(a[1]), "r"(a[2]), "r"(a[3]), "r"(b[0]), "r"(b[1]));
}

// ---------------- init ----------------
__global__ void init_kernel() {
    int i = blockIdx.x * blockDim.x + threadIdx.x;
    if (i < NCLS * F) g_fsum[i] = 0.f;
    if (i < NCLS)     g_counts[i] = 0;
    if (i == 0) { g_s2 = 0.0; g_ce = 0.0; g_l1 = 0.0; g_acc = 0.0; }
}

// ---------------- transposes ----------------
__global__ __launch_bounds__(1024) void transpose_fc(
    const float* __restrict__ fc0, const float* __restrict__ fc1)
{
    __shared__ float t0[32][33];
    __shared__ float t1[32][33];
    int bx = blockIdx.x * 32, by = blockIdx.y * 32;
    int txi = threadIdx.x, tyi = threadIdx.y;
    t0[tyi][txi] = fc0[(by + tyi) * F + bx + txi];
    t1[tyi][txi] = fc1[(by + tyi) * F + bx + txi];
    __syncthreads();
    g_fc0T[(bx + tyi) * F + by + txi] = t0[txi][tyi];
    g_fc1T[(bx + tyi) * F + by + txi] = t1[txi][tyi];
}
__global__ __launch_bounds__(1024) void transpose_w(const float* __restrict__ w) {
    __shared__ float t[32][33];
    int bx = blockIdx.x * 32, by = blockIdx.y * 32;
    t[threadIdx.y][threadIdx.x] = w[(by + threadIdx.y) * HID + bx + threadIdx.x];
    __syncthreads();
    g_wT[(size_t)(bx + threadIdx.y) * F + by + threadIdx.x] = t[threadIdx.x][threadIdx.y];
}

// ---------------- histogram ----------------
__global__ void hist_kernel(const int* __restrict__ y) {
    __shared__ int h[NCLS];
    if (threadIdx.x < NCLS) h[threadIdx.x] = 0;
    __syncthreads();
    int i = blockIdx.x * blockDim.x + threadIdx.x;
    int stride = gridDim.x * blockDim.x;
    for (; i < BATCH; i += stride) atomicAdd(&h[y[i]], 1);
    __syncthreads();
    if (threadIdx.x < NCLS) atomicAdd(&g_counts[threadIdx.x], h[threadIdx.x]);
}

// ============ gate: x4 = x + (1+sigmoid(x@fc0))*relu(x@fc1), tf32 mma ============
// CTA: 128 rows x 64 logical cols (fc0 & fc1 both). B smem has 128 cols:
// logical col L of matrix m lives at smem col nb = 16*(L>>3) + 8*m + (L&7),
// so n-tile pairs (2j, 2j+1) give matched acc0/acc1 at identical (row, col).
#define GS 36  // smem row stride (floats): banks (4*g + tig) unique per quad-group
#define G_AS  0
#define G_BS  (128 * GS)
#define G_CS  (G_BS + 128 * GS)
#define G_RED (G_CS + NCLS * 68)
#define GATE_SMEM_FLOATS (G_RED + 8)

__global__ __launch_bounds__(256, 1) void gate_kernel(
    const float* __restrict__ x, const int* __restrict__ y)
{
    extern __shared__ float sm[];
    float* As   = sm + G_AS;
    float* Bs   = sm + G_BS;
    float* csum = sm + G_CS;
    float* red  = sm + G_RED;

    const int tid = threadIdx.x;
    const int lane = tid & 31, wid = tid >> 5;
    const int g = lane >> 2, tig = lane & 3;
    const int warpM = wid & 3, warpN = wid >> 2;
    const int rowBase = blockIdx.y * 128;
    const int colBase = blockIdx.x * 64;

    for (int i = tid; i < NCLS * 68; i += 256) csum[i] = 0.f;

    float acc[2][8][4];
#pragma unroll
    for (int mt = 0; mt < 2; mt++)
#pragma unroll
        for (int nt = 0; nt < 8; nt++)
#pragma unroll
            for (int r = 0; r < 4; r++) acc[mt][nt][r] = 0.f;

    float4 pa[4], p0[2], p1[2];
    // prefetch chunk 0
    {
        const int kb = 0;
#pragma unroll
        for (int l = 0; l < 4; l++) {
            int idx = tid + l * 256, r = idx >> 3, q = idx & 7;
            pa[l] = *(const float4*)&x[(size_t)(rowBase + r) * F + kb + q * 4];
        }
#pragma unroll
        for (int l = 0; l < 2; l++) {
            int idx = tid + l * 256, L = idx >> 3, q = idx & 7;
            p0[l] = *(const float4*)&g_fc0T[(size_t)(colBase + L) * F + kb + q * 4];
            p1[l] = *(const float4*)&g_fc1T[(size_t)(colBase + L) * F + kb + q * 4];
        }
    }

    for (int ch = 0; ch < 16; ch++) {
        // STS (with tf32 convert)
#pragma unroll
        for (int l = 0; l < 4; l++) {
            int idx = tid + l * 256, r = idx >> 3, q = idx & 7;
            float* d = &As[r * GS + q * 4];
            d[0] = __uint_as_float(f2tf32(pa[l].x));
            d[1] = __uint_as_float(f2tf32(pa[l].y));
            d[2] = __uint_as_float(f2tf32(pa[l].z));
            d[3] = __uint_as_float(f2tf32(pa[l].w));
        }
#pragma unroll
        for (int l = 0; l < 2; l++) {
            int idx = tid + l * 256, L = idx >> 3, q = idx & 7;
            int nb0 = 16 * (L >> 3) + (L & 7);
            float* d0 = &Bs[nb0 * GS + q * 4];
            d0[0] = __uint_as_float(f2tf32(p0[l].x));
            d0[1] = __uint_as_float(f2tf32(p0[l].y));
            d0[2] = __uint_as_float(f2tf32(p0[l].z));
            d0[3] = __uint_as_float(f2tf32(p0[l].w));
            float* d1 = &Bs[(nb0 + 8) * GS + q * 4];
            d1[0] = __uint_as_float(f2tf32(p1[l].x));
            d1[1] = __uint_as_float(f2tf32(p1[l].y));
            d1[2] = __uint_as_float(f2tf32(p1[l].z));
            d1[3] = __uint_as_float(f2tf32(p1[l].w));
        }
        __syncthreads();

        if (ch < 15) {  // prefetch next chunk (overlaps with mma below)
            const int kb = (ch + 1) * 32;
#pragma unroll
            for (int l = 0; l < 4; l++) {
                int idx = tid + l * 256, r = idx >> 3, q = idx & 7;
                pa[l] = *(const float4*)&x[(size_t)(rowBase + r) * F + kb + q * 4];
            }
#pragma unroll
            for (int l = 0; l < 2; l++) {
                int idx = tid + l * 256, L = idx >> 3, q = idx & 7;
                p0[l] = *(const float4*)&g_fc0T[(size_t)(colBase + L) * F + kb + q * 4];
                p1[l] = *(const float4*)&g_fc1T[(size_t)(colBase + L) * F + kb + q * 4];
            }
        }

#pragma unroll
        for (int s = 0; s < 4; s++) {
            uint32_t a[2][4], b[8][2];
#pragma unroll
            for (int mt = 0; mt < 2; mt++) {
                int r0 = warpM * 32 + mt * 16 + g;
                a[mt][0] = __float_as_uint(As[r0 * GS + s * 8 + tig]);
                a[mt][1] = __float_as_uint(As[(r0 + 8) * GS + s * 8 + tig]);
                a[mt][2] = __float_as_uint(As[r0 * GS + s * 8 + tig + 4]);
                a[mt][3] = __float_as_uint(As[(r0 + 8) * GS + s * 8 + tig + 4]);
            }
#pragma unroll
            for (int nt = 0; nt < 8; nt++) {
                int nb = warpN * 64 + nt * 8 + g;
                b[nt][0] = __float_as_uint(Bs[nb * GS + s * 8 + tig]);
                b[nt][1] = __float_as_uint(Bs[nb * GS + s * 8 + tig + 4]);
            }
#pragma unroll
            for (int mt = 0; mt < 2; mt++)
#pragma unroll
                for (int nt = 0; nt < 8; nt++)
                    mma_tf32(acc[mt][nt], a[mt], b[nt]);
        }
        __syncthreads();
    }

    // ---- epilogue ----
    float s2loc = 0.f;
#pragma unroll
    for (int mt = 0; mt < 2; mt++) {
        int r0 = rowBase + warpM * 32 + mt * 16 + g;
        int r1 = r0 + 8;
        int y0 = y[r0], y1 = y[r1];
#pragma unroll
        for (int j = 0; j < 4; j++) {
            int lcol = warpN * 32 + j * 8 + 2 * tig;
            int gcol = colBase + lcol;
            // row r0 (regs 0,1)
            {
                float A0x = acc[mt][2 * j][0], A0y = acc[mt][2 * j][1];
                float A1x = acc[mt][2 * j + 1][0], A1y = acc[mt][2 * j + 1][1];
                float2 xv = *(const float2*)&x[(size_t)r0 * F + gcol];
                float ox = xv.x + (1.f + 1.f / (1.f + expf(-A0x))) * fmaxf(A1x, 0.f);
                float oy = xv.y + (1.f + 1.f / (1.f + expf(-A0y))) * fmaxf(A1y, 0.f);
                *(float2*)&g_x4[(size_t)r0 * F + gcol] = make_float2(ox, oy);
                s2loc += ox * ox + oy * oy;
                atomicAdd(&csum[y0 * 68 + lcol], ox);
                atomicAdd(&csum[y0 * 68 + lcol + 1], oy);
            }
            // row r1 (regs 2,3)
            {
                float A0x = acc[mt][2 * j][2], A0y = acc[mt][2 * j][3];
                float A1x = acc[mt][2 * j + 1][2], A1y = acc[mt][2 * j + 1][3];
                float2 xv = *(const float2*)&x[(size_t)r1 * F + gcol];
                float ox = xv.x + (1.f + 1.f / (1.f + expf(-A0x))) * fmaxf(A1x, 0.f);
                float oy = xv.y + (1.f + 1.f / (1.f + expf(-A0y))) * fmaxf(A1y, 0.f);
                *(float2*)&g_x4[(size_t)r1 * F + gcol] = make_float2(ox, oy);
                s2loc += ox * ox + oy * oy;
                atomicAdd(&csum[y1 * 68 + lcol], ox);
                atomicAdd(&csum[y1 * 68 + lcol + 1], oy);
            }
        }
    }
    __syncthreads();

    for (int i = tid; i < NCLS * 64; i += 256) {
        int c = i >> 6, col = i & 63;
        float v = csum[c * 68 + col];
        if (v != 0.f) atomicAdd(&g_fsum[c * F + colBase + col], v);
    }
#pragma unroll
    for (int o = 16; o; o >>= 1) s2loc += __shfl_xor_sync(0xffffffffu, s2loc, o);
    if (lane == 0) red[wid] = s2loc;
    __syncthreads();
    if (tid == 0) {
        float t = 0.f;
        for (int i = 0; i < 8; i++) t += red[i];
        atomicAdd(&g_s2, (double)t);
    }
}

// ---------------- L1 ----------------
__global__ void l1_kernel(const float* __restrict__ fc0, const float* __restrict__ fc1,
                          const float* __restrict__ w, const float* __restrict__ w1)
{
    float s = 0.f;
    int i0 = blockIdx.x * blockDim.x + threadIdx.x;
    int stride = gridDim.x * blockDim.x;
    for (int k = i0; k < F * F; k += stride) s += fabsf(fc0[k]) + fabsf(fc1[k]);
    for (int k = i0; k < F * HID; k += stride) s += fabsf(w[k]);
    for (int k = i0; k < HID * NCLS; k += stride) s += fabsf(w1[k]);
#pragma unroll
    for (int o = 16; o; o >>= 1) s += __shfl_xor_sync(0xffffffffu, s, o);
    __shared__ float red[8];
    if ((threadIdx.x & 31) == 0) red[threadIdx.x >> 5] = s;
    __syncthreads();
    if (threadIdx.x == 0) {
        float t = 0.f;
        for (int i = 0; i < 8; i++) t += red[i];
        atomicAdd(&g_l1, (double)t);
    }
}

// ============ head: logits = relu(x4@w)@w1, 3xTF32 mma, CE + acc ============
// CTA: 64 rows x HID(256). 8 warps, each warp: M=64, N=32 slice.
#define H_AH  0
#define H_AL  (64 * GS)
#define H_WH  (H_AL + 64 * GS)
#define H_WL  (H_WH + 256 * GS)
#define H_W1  (H_WL + 256 * GS)
#define H_PART (H_W1 + NCLS * 260)
#define H_LOG (H_PART + 8 * 64 * NCLS)
#define HEAD_SMEM_FLOATS (H_LOG + 64 * NCLS)

__global__ __launch_bounds__(256, 1) void head_kernel(
    const float* __restrict__ w1, const int* __restrict__ y)
{
    extern __shared__ float sm[];
    float* AH  = sm + H_AH;
    float* AL  = sm + H_AL;
    float* WH  = sm + H_WH;
    float* WL  = sm + H_WL;
    float* w1t = sm + H_W1;
    float* part = sm + H_PART;
    float* logits = sm + H_LOG;

    const int tid = threadIdx.x;
    const int lane = tid & 31, wid = tid >> 5;
    const int g = lane >> 2, tig = lane & 3;
    const int rowBase = blockIdx.x * 64;

    for (int i = tid; i < HID * NCLS; i += 256) {
        int jj = i / NCLS, c = i % NCLS;
        w1t[c * 260 + jj] = w1[i];
    }

    float acc[4][4][4];
#pragma unroll
    for (int mt = 0; mt < 4; mt++)
#pragma unroll
        for (int nt = 0; nt < 4; nt++)
#pragma unroll
            for (int r = 0; r < 4; r++) acc[mt][nt][r] = 0.f;

    float4 pa[2], pb[8];
    {
        const int kb = 0;
#pragma unroll
        for (int l = 0; l < 2; l++) {
            int idx = tid + l * 256, r = idx >> 3, q = idx & 7;
            pa[l] = *(const float4*)&g_x4[(size_t)(rowBase + r) * F + kb + q * 4];
        }
#pragma unroll
        for (int l = 0; l < 8; l++) {
            int idx = tid + l * 256, nb = idx >> 3, q = idx & 7;
            pb[l] = *(const float4*)&g_wT[(size_t)nb * F + kb + q * 4];
        }
    }

    for (int ch = 0; ch < 16; ch++) {
#pragma unroll
        for (int l = 0; l < 2; l++) {
            int idx = tid + l * 256, r = idx >> 3, q = idx & 7;
            float v[4] = {pa[l].x, pa[l].y, pa[l].z, pa[l].w};
#pragma unroll
            for (int e = 0; e < 4; e++) {
                uint32_t hb = f2tf32(v[e]);
                float hf = __uint_as_float(hb);
                AH[r * GS + q * 4 + e] = hf;
                AL[r * GS + q * 4 + e] = __uint_as_float(f2tf32(v[e] - hf));
            }
        }
#pragma unroll
        for (int l = 0; l < 8; l++) {
            int idx = tid + l * 256, nb = idx >> 3, q = idx & 7;
            float v[4] = {pb[l].x, pb[l].y, pb[l].z, pb[l].w};
#pragma unroll
            for (int e = 0; e < 4; e++) {
                uint32_t hb = f2tf32(v[e]);
                float hf = __uint_as_float(hb);
                WH[nb * GS + q * 4 + e] = hf;
                WL[nb * GS + q * 4 + e] = __uint_as_float(f2tf32(v[e] - hf));
            }
        }
        __syncthreads();

        if (ch < 15) {
            const int kb = (ch + 1) * 32;
#pragma unroll
            for (int l = 0; l < 2; l++) {
                int idx = tid + l * 256, r = idx >> 3, q = idx & 7;
                pa[l] = *(const float4*)&g_x4[(size_t)(rowBase + r) * F + kb + q * 4];
            }
#pragma unroll
            for (int l = 0; l < 8; l++) {
                int idx = tid + l * 256, nb = idx >> 3, q = idx & 7;
                pb[l] = *(const float4*)&g_wT[(size_t)nb * F + kb + q * 4];
            }
        }

#pragma unroll
        for (int s = 0; s < 4; s++) {
            uint32_t ah[4][4], al[4][4], bh[4][2], bl[4][2];
#pragma unroll
            for (int mt = 0; mt < 4; mt++) {
                int r0 = mt * 16 + g;
                ah[mt][0] = __float_as_uint(AH[r0 * GS + s * 8 + tig]);
                ah[mt][1] = __float_as_uint(AH[(r0 + 8) * GS + s * 8 + tig]);
                ah[mt][2] = __float_as_uint(AH[r0 * GS + s * 8 + tig + 4]);
                ah[mt][3] = __float_as_uint(AH[(r0 + 8) * GS + s * 8 + tig + 4]);
                al[mt][0] = __float_as_uint(AL[r0 * GS + s * 8 + tig]);
                al[mt][1] = __float_as_uint(AL[(r0 + 8) * GS + s * 8 + tig]);
                al[mt][2] = __float_as_uint(AL[r0 * GS + s * 8 + tig + 4]);
                al[mt][3] = __float_as_uint(AL[(r0 + 8) * GS + s * 8 + tig + 4]);
            }
#pragma unroll
            for (int nt = 0; nt < 4; nt++) {
                int nb = wid * 32 + nt * 8 + g;
                bh[nt][0] = __float_as_uint(WH[nb * GS + s * 8 + tig]);
                bh[nt][1] = __float_as_uint(WH[nb * GS + s * 8 + tig + 4]);
                bl[nt][0] = __float_as_uint(WL[nb * GS + s * 8 + tig]);
                bl[nt][1] = __float_as_uint(WL[nb * GS + s * 8 + tig + 4]);
            }
#pragma unroll
            for (int mt = 0; mt < 4; mt++)
#pragma unroll
                for (int nt = 0; nt < 4; nt++) {
                    mma_tf32(acc[mt][nt], al[mt], bh[nt]);
                    mma_tf32(acc[mt][nt], ah[mt], bl[nt]);
                    mma_tf32(acc[mt][nt], ah[mt], bh[nt]);
                }
        }
        __syncthreads();
    }

    // relu in place
#pragma unroll
    for (int mt = 0; mt < 4; mt++)
#pragma unroll
        for (int nt = 0; nt < 4; nt++)
#pragma unroll
            for (int r = 0; r < 4; r++) acc[mt][nt][r] = fmaxf(acc[mt][nt][r], 0.f);

    // partial logits: quad-reduce over tig, store per-warp partials
#pragma unroll
    for (int c = 0; c < NCLS; c++) {
        float w1v[8];
#pragma unroll
        for (int nt = 0; nt < 4; nt++) {
            int col = wid * 32 + nt * 8 + 2 * tig;
            w1v[nt * 2]     = w1t[c * 260 + col];
            w1v[nt * 2 + 1] = w1t[c * 260 + col + 1];
        }
#pragma unroll
        for (int mt = 0; mt < 4; mt++)
#pragma unroll
            for (int rr = 0; rr < 2; rr++) {
                float s = 0.f;
#pragma unroll
                for (int nt = 0; nt < 4; nt++) {
                    s += acc[mt][nt][rr * 2]     * w1v[nt * 2];
                    s += acc[mt][nt][rr * 2 + 1] * w1v[nt * 2 + 1];
                }
                s += __shfl_xor_sync(0xffffffffu, s, 1);
                s += __shfl_xor_sync(0xffffffffu, s, 2);
                if (tig == 0)
                    part[wid * (64 * NCLS) + (mt * 16 + g + rr * 8) * NCLS + c] = s;
            }
    }
    __syncthreads();

    // combine warps
    for (int i = tid; i < 64 * NCLS; i += 256) {
        float t = 0.f;
#pragma unroll
        for (int wz = 0; wz < 8; wz++) t += part[wz * (64 * NCLS) + i];
        logits[i] = t;
    }
    __syncthreads();

    // softmax / CE / argmax for 64 rows
    float ce_loc = 0.f, corr_loc = 0.f;
    if (tid < 64) {
        int row = rowBase + tid;
        int yr = y[row];
        const float* lg = &logits[tid * NCLS];
        float m = lg[0]; int bi = 0;
#pragma unroll
        for (int c = 1; c < NCLS; c++) if (lg[c] > m) { m = lg[c]; bi = c; }
        float se = 0.f;
#pragma unroll
        for (int c = 0; c < NCLS; c++) se += expf(lg[c] - m);
        ce_loc = (m + logf(se)) - lg[yr];
        corr_loc = (bi == yr) ? 1.f : 0.f;
    }
    if (tid < 64) {
#pragma unroll
        for (int o = 16; o; o >>= 1) {
            ce_loc += __shfl_xor_sync(0xffffffffu, ce_loc, o);
            corr_loc += __shfl_xor_sync(0xffffffffu, corr_loc, o);
        }
        if ((tid & 31) == 0) {
            atomicAdd(&g_ce, (double)ce_loc);
            atomicAdd(&g_acc, (double)corr_loc);
        }
    }
}

// ---------------- finalize ----------------
__global__ void final_kernel(float* __restrict__ out) {
    int tid = threadIdx.x;
    float t = 0.f;
    for (int i = tid; i < NCLS * F; i += 256) {
        int c = i / F;
        int cnt = g_counts[c]; if (cnt < 1) cnt = 1;
        float v = g_fsum[i];
        t += v * v / (float)cnt;
    }
#pragma unroll
    for (int o = 16; o; o >>= 1) t += __shfl_xor_sync(0xffffffffu, t, o);
    __shared__ float red[8];
    if ((tid & 31) == 0) red[tid >> 5] = t;
    __syncthreads();
    if (tid == 0) {
        double tt = 0.0;
        for (int i = 0; i < 8; i++) tt += (double)red[i];
        double var = g_s2 - tt;
        double loss = g_ce / (double)BATCH + 1e-4 * g_l1 + 1e-3 * var;
        out[0] = (float)loss;
        out[1] = (float)(g_acc / (double)BATCH);
    }
}

// ---------------- launch ----------------
extern "C" void kernel_launch(void* const* d_in, const int* in_sizes, int n_in,
                              void* d_out, int out_size) {
    const float* x   = (const float*)d_in[0];
    const int*   y   = (const int*)d_in[1];
    const float* fc0 = (const float*)d_in[2];
    const float* fc1 = (const float*)d_in[3];
    const float* w   = (const float*)d_in[4];
    const float* w1  = (const float*)d_in[5];
    float* out = (float*)d_out;

    static int configured = 0;
    if (!configured) {
        cudaFuncSetAttribute(gate_kernel, cudaFuncAttributeMaxDynamicSharedMemorySize,
                             GATE_SMEM_FLOATS * 4);
        cudaFuncSetAttribute(head_kernel, cudaFuncAttributeMaxDynamicSharedMemorySize,
                             HEAD_SMEM_FLOATS * 4);
        configured = 1;
    }

    init_kernel<<<20, 256>>>();
    transpose_fc<<<dim3(F / 32, F / 32), dim3(32, 32)>>>(fc0, fc1);
    transpose_w<<<dim3(HID / 32, F / 32), dim3(32, 32)>>>(w);
    hist_kernel<<<64, 256>>>(y);
    gate_kernel<<<dim3(F / 64, BATCH / 128), 256, GATE_SMEM_FLOATS * 4>>>(x, y);
    l1_kernel<<<256, 256>>>(fc0, fc1, w, w1);
    head_kernel<<<BATCH / 64, 256, HEAD_SMEM_FLOATS * 4>>>(w1, y);
    final_kernel<<<1, 256>>>(out);
}

// round 4
// speedup vs baseline: 2.8879x; 1.5925x over previous
#include <cuda_runtime.h>
#include <math.h>
#include <stdint.h>

#define BATCH 65536
#define F     512
#define HID   256
#define NCLS  10

// ---------------- scratch ----------------
__device__ float  g_x4[(size_t)BATCH * F];   // 128 MB
__device__ float  g_fc0T[F * F];
__device__ float  g_fc1T[F * F];
__device__ float  g_wHiT[HID * F];
__device__ float  g_wLoT[HID * F];
__device__ float  g_fsum[NCLS * F];
__device__ int    g_counts[NCLS];
__device__ double g_s2, g_ce, g_l1, g_acc;

// ---------------- helpers ----------------
__device__ __forceinline__ uint32_t smem_u32(const void* p) {
    uint32_t a;
    asm("{ .reg .u64 t; cvta.to.shared.u64 t, %1; cvt.u32.u64 %0, t; }"
        : "=r"(a) : "l"(p));
    return a;
}
__device__ __forceinline__ void cpasync16(uint32_t dst, const void* src) {
    asm volatile("cp.async.cg.shared.global [%0], [%1], 16;"
                 :: "r"(dst), "l"(src) : "memory");
}
#define CP_COMMIT() asm volatile("cp.async.commit_group;" ::: "memory")
#define CP_WAIT(n)  asm volatile("cp.async.wait_group %0;" :: "n"(n) : "memory")

__device__ __forceinline__ float tf32_hi(float f) {
    return __uint_as_float(__float_as_uint(f) & 0xFFFFE000u);
}
__device__ __forceinline__ void mma_tf32(float* c, const uint32_t* a, const uint32_t* b) {
    asm volatile("mma.sync.aligned.m16n8k8.row.col.f32.tf32.tf32.f32 "
                 "{%0,%1,%2,%3}, {%4,%5,%6,%7}, {%8,%9}, {%0,%1,%2,%3};"
                 : "+f"(c[0]), "+f"(c[1]), "+f"(c[2]), "+f"(c[3])
                 : "r"(a[0]), "r"(a[1]), "r"(a[2]), "r"(a[3]), "r"(b[0]), "r"(b[1]));
}

// ---------------- init ----------------
__global__ void init_kernel() {
    int i = blockIdx.x * blockDim.x + threadIdx.x;
    if (i < NCLS * F) g_fsum[i] = 0.f;
    if (i < NCLS)     g_counts[i] = 0;
    if (i == 0) { g_s2 = 0.0; g_ce = 0.0; g_l1 = 0.0; g_acc = 0.0; }
}

// ---------------- transposes ----------------
__global__ __launch_bounds__(1024) void transpose_fc(
    const float* __restrict__ fc0, const float* __restrict__ fc1)
{
    __shared__ float t0[32][33];
    __shared__ float t1[32][33];
    int bx = blockIdx.x * 32, by = blockIdx.y * 32;
    int txi = threadIdx.x, tyi = threadIdx.y;
    t0[tyi][txi] = fc0[(by + tyi) * F + bx + txi];
    t1[tyi][txi] = fc1[(by + tyi) * F + bx + txi];
    __syncthreads();
    g_fc0T[(bx + tyi) * F + by + txi] = t0[txi][tyi];
    g_fc1T[(bx + tyi) * F + by + txi] = t1[txi][tyi];
}
__global__ __launch_bounds__(1024) void transpose_w(const float* __restrict__ w) {
    __shared__ float t[32][33];
    int bx = blockIdx.x * 32, by = blockIdx.y * 32;
    t[threadIdx.y][threadIdx.x] = w[(by + threadIdx.y) * HID + bx + threadIdx.x];
    __syncthreads();
    float v = t[threadIdx.x][threadIdx.y];
    float hi = tf32_hi(v);
    size_t o = (size_t)(bx + threadIdx.y) * F + by + threadIdx.x;
    g_wHiT[o] = hi;
    g_wLoT[o] = v - hi;
}

// ---------------- histogram ----------------
__global__ void hist_kernel(const int* __restrict__ y) {
    __shared__ int h[NCLS];
    if (threadIdx.x < NCLS) h[threadIdx.x] = 0;
    __syncthreads();
    int i = blockIdx.x * blockDim.x + threadIdx.x;
    int stride = gridDim.x * blockDim.x;
    for (; i < BATCH; i += stride) atomicAdd(&h[y[i]], 1);
    __syncthreads();
    if (threadIdx.x < NCLS) atomicAdd(&g_counts[threadIdx.x], h[threadIdx.x]);
}

// ============ gate: x4 = x + (1+sigmoid(x@fc0))*relu(x@fc1) ============
// CTA: 128 rows x 64 logical cols for both matrices (interleaved in B smem).
// 3-stage cp.async pipeline, XOR-swizzled smem, raw fp32 fed to tf32 HMMA.
#define G_STAGE_FL 8192              // A 4096 + B 4096 floats
#define G_CSUM_FL  (3 * G_STAGE_FL)  // 24576
#define G_RED_FL   (G_CSUM_FL + NCLS * 68)
#define GATE_FL    (G_RED_FL + 8)

__global__ __launch_bounds__(256, 2) void gate_kernel(
    const float* __restrict__ x, const int* __restrict__ y)
{
    extern __shared__ float sm[];
    const uint32_t smb = smem_u32(sm);
    float* csum = sm + G_CSUM_FL;
    float* red  = sm + G_RED_FL;

    const int tid = threadIdx.x;
    const int lane = tid & 31, wid = tid >> 5;
    const int g = lane >> 2, tig = lane & 3;
    const int warpM = wid & 3, warpN = wid >> 2;
    const int rowBase = blockIdx.y * 128;
    const int colBase = blockIdx.x * 64;

    for (int i = tid; i < NCLS * 68; i += 256) csum[i] = 0.f;

    float acc[2][8][4];
#pragma unroll
    for (int mt = 0; mt < 2; mt++)
#pragma unroll
        for (int nt = 0; nt < 8; nt++)
#pragma unroll
            for (int r = 0; r < 4; r++) acc[mt][nt][r] = 0.f;

    auto issue = [&](int ch) {
        const int p = ch % 3;
        const uint32_t sA = smb + p * (G_STAGE_FL * 4);
        const uint32_t sB = sA + 16384;
        const int kb = ch * 32;
#pragma unroll
        for (int l = 0; l < 4; l++) {
            int idx = l * 256 + tid;
            int r = idx >> 3, q = idx & 7;
            cpasync16(sA + (r * 8 + (q ^ (r & 7))) * 16,
                      &x[(size_t)(rowBase + r) * F + kb + q * 4]);
        }
#pragma unroll
        for (int l = 0; l < 4; l++) {
            int idx = l * 256 + tid;
            int nb = idx >> 3, q = idx & 7;
            int m = (nb >> 3) & 1;
            int L = ((nb >> 4) << 3) | (nb & 7);
            const float* src = (m ? g_fc1T : g_fc0T)
                             + (size_t)(colBase + L) * F + kb + q * 4;
            cpasync16(sB + (nb * 8 + (q ^ (nb & 7))) * 16, src);
        }
        CP_COMMIT();
    };

    issue(0);
    issue(1);

    for (int ch = 0; ch < 16; ch++) {
        if (ch < 14) issue(ch + 2); else CP_COMMIT();
        CP_WAIT(2);
        __syncthreads();

        const float* As = sm + (ch % 3) * G_STAGE_FL;
        const float* Bs = As + 4096;
#pragma unroll
        for (int s = 0; s < 4; s++) {
            const int x0 = (2 * s) ^ g;
            const int x1 = x0 ^ 1;
            uint32_t a[2][4], b[8][2];
#pragma unroll
            for (int mt = 0; mt < 2; mt++) {
                int r0 = warpM * 32 + mt * 16 + g;
                a[mt][0] = __float_as_uint(As[r0 * 32 + (x0 << 2) + tig]);
                a[mt][1] = __float_as_uint(As[(r0 + 8) * 32 + (x0 << 2) + tig]);
                a[mt][2] = __float_as_uint(As[r0 * 32 + (x1 << 2) + tig]);
                a[mt][3] = __float_as_uint(As[(r0 + 8) * 32 + (x1 << 2) + tig]);
            }
#pragma unroll
            for (int nt = 0; nt < 8; nt++) {
                int nb = warpN * 64 + nt * 8 + g;
                b[nt][0] = __float_as_uint(Bs[nb * 32 + (x0 << 2) + tig]);
                b[nt][1] = __float_as_uint(Bs[nb * 32 + (x1 << 2) + tig]);
            }
#pragma unroll
            for (int mt = 0; mt < 2; mt++)
#pragma unroll
                for (int nt = 0; nt < 8; nt++)
                    mma_tf32(acc[mt][nt], a[mt], b[nt]);
        }
        __syncthreads();
    }

    // ---- epilogue ----
    float s2loc = 0.f;
#pragma unroll
    for (int mt = 0; mt < 2; mt++) {
        int r0 = rowBase + warpM * 32 + mt * 16 + g;
        int r1 = r0 + 8;
        int y0 = y[r0], y1 = y[r1];
#pragma unroll
        for (int j = 0; j < 4; j++) {
            int lcol = warpN * 32 + j * 8 + 2 * tig;
            int gcol = colBase + lcol;
            {
                float A0x = acc[mt][2 * j][0], A0y = acc[mt][2 * j][1];
                float A1x = acc[mt][2 * j + 1][0], A1y = acc[mt][2 * j + 1][1];
                float2 xv = *(const float2*)&x[(size_t)r0 * F + gcol];
                float ox = xv.x + (1.f + 1.f / (1.f + expf(-A0x))) * fmaxf(A1x, 0.f);
                float oy = xv.y + (1.f + 1.f / (1.f + expf(-A0y))) * fmaxf(A1y, 0.f);
                *(float2*)&g_x4[(size_t)r0 * F + gcol] = make_float2(ox, oy);
                s2loc += ox * ox + oy * oy;
                atomicAdd(&csum[y0 * 68 + lcol], ox);
                atomicAdd(&csum[y0 * 68 + lcol + 1], oy);
            }
            {
                float A0x = acc[mt][2 * j][2], A0y = acc[mt][2 * j][3];
                float A1x = acc[mt][2 * j + 1][2], A1y = acc[mt][2 * j + 1][3];
                float2 xv = *(const float2*)&x[(size_t)r1 * F + gcol];
                float ox = xv.x + (1.f + 1.f / (1.f + expf(-A0x))) * fmaxf(A1x, 0.f);
                float oy = xv.y + (1.f + 1.f / (1.f + expf(-A0y))) * fmaxf(A1y, 0.f);
                *(float2*)&g_x4[(size_t)r1 * F + gcol] = make_float2(ox, oy);
                s2loc += ox * ox + oy * oy;
                atomicAdd(&csum[y1 * 68 + lcol], ox);
                atomicAdd(&csum[y1 * 68 + lcol + 1], oy);
            }
        }
    }
    __syncthreads();

    for (int i = tid; i < NCLS * 64; i += 256) {
        int c = i >> 6, col = i & 63;
        float v = csum[c * 68 + col];
        if (v != 0.f) atomicAdd(&g_fsum[c * F + colBase + col], v);
    }
#pragma unroll
    for (int o = 16; o; o >>= 1) s2loc += __shfl_xor_sync(0xffffffffu, s2loc, o);
    if (lane == 0) red[wid] = s2loc;
    __syncthreads();
    if (tid == 0) {
        float t = 0.f;
        for (int i = 0; i < 8; i++) t += red[i];
        atomicAdd(&g_s2, (double)t);
    }
}

// ---------------- L1 ----------------
__global__ void l1_kernel(const float* __restrict__ fc0, const float* __restrict__ fc1,
                          const float* __restrict__ w, const float* __restrict__ w1)
{
    float s = 0.f;
    int i0 = blockIdx.x * blockDim.x + threadIdx.x;
    int stride = gridDim.x * blockDim.x;
    for (int k = i0; k < F * F; k += stride) s += fabsf(fc0[k]) + fabsf(fc1[k]);
    for (int k = i0; k < F * HID; k += stride) s += fabsf(w[k]);
    for (int k = i0; k < HID * NCLS; k += stride) s += fabsf(w1[k]);
#pragma unroll
    for (int o = 16; o; o >>= 1) s += __shfl_xor_sync(0xffffffffu, s, o);
    __shared__ float red[8];
    if ((threadIdx.x & 31) == 0) red[threadIdx.x >> 5] = s;
    __syncthreads();
    if (threadIdx.x == 0) {
        float t = 0.f;
        for (int i = 0; i < 8; i++) t += red[i];
        atomicAdd(&g_l1, (double)t);
    }
}

// ============ head: logits = relu(x4@w)@w1, 3-term tf32 split ============
// CTA: 64 rows x 256 cols. 2-stage cp.async pipeline. A hi/lo derived in regs
// from raw x4 (hi = mask19(f), lo = f - hi). W hi/lo precomputed globally.
#define H_STAGE_FL 18432  // Araw 2048 + WH 8192 + WL 8192
#define H_W1_FL    (2 * H_STAGE_FL)          // 36864
#define H_PART_FL  (H_W1_FL + NCLS * 260)    // 39464
#define H_LOG_FL   (H_PART_FL + 8 * 64 * NCLS)
#define HEAD_FL    (H_LOG_FL + 64 * NCLS)

__global__ __launch_bounds__(256) void head_kernel(
    const float* __restrict__ w1, const int* __restrict__ y)
{
    extern __shared__ float sm[];
    const uint32_t smb = smem_u32(sm);
    float* w1t    = sm + H_W1_FL;
    float* part   = sm + H_PART_FL;
    float* logits = sm + H_LOG_FL;

    const int tid = threadIdx.x;
    const int lane = tid & 31, wid = tid >> 5;
    const int g = lane >> 2, tig = lane & 3;
    const int rowBase = blockIdx.x * 64;

    for (int i = tid; i < HID * NCLS; i += 256) {
        int jj = i / NCLS, c = i % NCLS;
        w1t[c * 260 + jj] = w1[i];
    }

    float acc[4][4][4];
#pragma unroll
    for (int mt = 0; mt < 4; mt++)
#pragma unroll
        for (int nt = 0; nt < 4; nt++)
#pragma unroll
            for (int r = 0; r < 4; r++) acc[mt][nt][r] = 0.f;

    auto issue = [&](int ch) {
        const int p = ch % 2;
        const uint32_t sA = smb + p * (H_STAGE_FL * 4);
        const uint32_t sH = sA + 2048 * 4;
        const uint32_t sL = sH + 8192 * 4;
        const int kb = ch * 32;
#pragma unroll
        for (int l = 0; l < 2; l++) {
            int idx = l * 256 + tid;
            int r = idx >> 3, q = idx & 7;
            cpasync16(sA + (r * 8 + (q ^ (r & 7))) * 16,
                      &g_x4[(size_t)(rowBase + r) * F + kb + q * 4]);
        }
#pragma unroll
        for (int l = 0; l < 8; l++) {
            int idx = l * 256 + tid;
            int nb = idx >> 3, q = idx & 7;
            uint32_t so = (nb * 8 + (q ^ (nb & 7))) * 16;
            cpasync16(sH + so, &g_wHiT[(size_t)nb * F + kb + q * 4]);
            cpasync16(sL + so, &g_wLoT[(size_t)nb * F + kb + q * 4]);
        }
        CP_COMMIT();
    };

    issue(0);

    for (int ch = 0; ch < 16; ch++) {
        if (ch < 15) issue(ch + 1); else CP_COMMIT();
        CP_WAIT(1);
        __syncthreads();

        const float* Ar  = sm + (ch % 2) * H_STAGE_FL;
        const float* WHs = Ar + 2048;
        const float* WLs = WHs + 8192;
#pragma unroll
        for (int s = 0; s < 4; s++) {
            const int x0 = (2 * s) ^ g;
            const int x1 = x0 ^ 1;
            uint32_t ah[4][4], al[4][4], bh[4][2], bl[4][2];
#pragma unroll
            for (int mt = 0; mt < 4; mt++) {
                int r0 = mt * 16 + g;
                float f0 = Ar[r0 * 32 + (x0 << 2) + tig];
                float f1 = Ar[(r0 + 8) * 32 + (x0 << 2) + tig];
                float f2 = Ar[r0 * 32 + (x1 << 2) + tig];
                float f3 = Ar[(r0 + 8) * 32 + (x1 << 2) + tig];
                float h0 = tf32_hi(f0), h1 = tf32_hi(f1);
                float h2 = tf32_hi(f2), h3 = tf32_hi(f3);
                ah[mt][0] = __float_as_uint(h0); al[mt][0] = __float_as_uint(f0 - h0);
                ah[mt][1] = __float_as_uint(h1); al[mt][1] = __float_as_uint(f1 - h1);
                ah[mt][2] = __float_as_uint(h2); al[mt][2] = __float_as_uint(f2 - h2);
                ah[mt][3] = __float_as_uint(h3); al[mt][3] = __float_as_uint(f3 - h3);
            }
#pragma unroll
            for (int nt = 0; nt < 4; nt++) {
                int nb = wid * 32 + nt * 8 + g;
                bh[nt][0] = __float_as_uint(WHs[nb * 32 + (x0 << 2) + tig]);
                bh[nt][1] = __float_as_uint(WHs[nb * 32 + (x1 << 2) + tig]);
                bl[nt][0] = __float_as_uint(WLs[nb * 32 + (x0 << 2) + tig]);
                bl[nt][1] = __float_as_uint(WLs[nb * 32 + (x1 << 2) + tig]);
            }
#pragma unroll
            for (int mt = 0; mt < 4; mt++)
#pragma unroll
                for (int nt = 0; nt < 4; nt++) {
                    mma_tf32(acc[mt][nt], al[mt], bh[nt]);
                    mma_tf32(acc[mt][nt], ah[mt], bl[nt]);
                    mma_tf32(acc[mt][nt], ah[mt], bh[nt]);
                }
        }
        __syncthreads();
    }

    // relu
#pragma unroll
    for (int mt = 0; mt < 4; mt++)
#pragma unroll
        for (int nt = 0; nt < 4; nt++)
#pragma unroll
            for (int r = 0; r < 4; r++) acc[mt][nt][r] = fmaxf(acc[mt][nt][r], 0.f);

    // partial logits
#pragma unroll
    for (int c = 0; c < NCLS; c++) {
        float w1v[8];
#pragma unroll
        for (int nt = 0; nt < 4; nt++) {
            int col = wid * 32 + nt * 8 + 2 * tig;
            w1v[nt * 2]     = w1t[c * 260 + col];
            w1v[nt * 2 + 1] = w1t[c * 260 + col + 1];
        }
#pragma unroll
        for (int mt = 0; mt < 4; mt++)
#pragma unroll
            for (int rr = 0; rr < 2; rr++) {
                float s = 0.f;
#pragma unroll
                for (int nt = 0; nt < 4; nt++) {
                    s += acc[mt][nt][rr * 2]     * w1v[nt * 2];
                    s += acc[mt][nt][rr * 2 + 1] * w1v[nt * 2 + 1];
                }
                s += __shfl_xor_sync(0xffffffffu, s, 1);
                s += __shfl_xor_sync(0xffffffffu, s, 2);
                if (tig == 0)
                    part[wid * (64 * NCLS) + (mt * 16 + g + rr * 8) * NCLS + c] = s;
            }
    }
    __syncthreads();

    for (int i = tid; i < 64 * NCLS; i += 256) {
        float t = 0.f;
#pragma unroll
        for (int wz = 0; wz < 8; wz++) t += part[wz * (64 * NCLS) + i];
        logits[i] = t;
    }
    __syncthreads();

    float ce_loc = 0.f, corr_loc = 0.f;
    if (tid < 64) {
        int row = rowBase + tid;
        int yr = y[row];
        const float* lg = &logits[tid * NCLS];
        float m = lg[0]; int bi = 0;
#pragma unroll
        for (int c = 1; c < NCLS; c++) if (lg[c] > m) { m = lg[c]; bi = c; }
        float se = 0.f;
#pragma unroll
        for (int c = 0; c < NCLS; c++) se += expf(lg[c] - m);
        ce_loc = (m + logf(se)) - lg[yr];
        corr_loc = (bi == yr) ? 1.f : 0.f;
#pragma unroll
        for (int o = 16; o; o >>= 1) {
            ce_loc += __shfl_xor_sync(0xffffffffu, ce_loc, o);
            corr_loc += __shfl_xor_sync(0xffffffffu, corr_loc, o);
        }
        if ((tid & 31) == 0) {
            atomicAdd(&g_ce, (double)ce_loc);
            atomicAdd(&g_acc, (double)corr_loc);
        }
    }
}

// ---------------- finalize ----------------
__global__ void final_kernel(float* __restrict__ out) {
    int tid = threadIdx.x;
    float t = 0.f;
    for (int i = tid; i < NCLS * F; i += 256) {
        int c = i / F;
        int cnt = g_counts[c]; if (cnt < 1) cnt = 1;
        float v = g_fsum[i];
        t += v * v / (float)cnt;
    }
#pragma unroll
    for (int o = 16; o; o >>= 1) t += __shfl_xor_sync(0xffffffffu, t, o);
    __shared__ float red[8];
    if ((tid & 31) == 0) red[tid >> 5] = t;
    __syncthreads();
    if (tid == 0) {
        double tt = 0.0;
        for (int i = 0; i < 8; i++) tt += (double)red[i];
        double var = g_s2 - tt;
        double loss = g_ce / (double)BATCH + 1e-4 * g_l1 + 1e-3 * var;
        out[0] = (float)loss;
        out[1] = (float)(g_acc / (double)BATCH);
    }
}

// ---------------- launch ----------------
extern "C" void kernel_launch(void* const* d_in, const int* in_sizes, int n_in,
                              void* d_out, int out_size) {
    const float* x   = (const float*)d_in[0];
    const int*   y   = (const int*)d_in[1];
    const float* fc0 = (const float*)d_in[2];
    const float* fc1 = (const float*)d_in[3];
    const float* w   = (const float*)d_in[4];
    const float* w1  = (const float*)d_in[5];
    float* out = (float*)d_out;

    static int configured = 0;
    if (!configured) {
        cudaFuncSetAttribute(gate_kernel, cudaFuncAttributeMaxDynamicSharedMemorySize,
                             GATE_FL * 4);
        cudaFuncSetAttribute(head_kernel, cudaFuncAttributeMaxDynamicSharedMemorySize,
                             HEAD_FL * 4);
        configured = 1;
    }

    init_kernel<<<20, 256>>>();
    transpose_fc<<<dim3(F / 32, F / 32), dim3(32, 32)>>>(fc0, fc1);
    transpose_w<<<dim3(HID / 32, F / 32), dim3(32, 32)>>>(w);
    hist_kernel<<<64, 256>>>(y);
    gate_kernel<<<dim3(F / 64, BATCH / 128), 256, GATE_FL * 4>>>(x, y);
    l1_kernel<<<256, 256>>>(fc0, fc1, w, w1);
    head_kernel<<<BATCH / 64, 256, HEAD_FL * 4>>>(w1, y);
    final_kernel<<<1, 256>>>(out);
}

// round 5
// speedup vs baseline: 2.9668x; 1.0273x over previous
#include <cuda_runtime.h>
#include <math.h>
#include <stdint.h>

#define BATCH 65536
#define F     512
#define HID   256
#define NCLS  10

// ---------------- scratch ----------------
__device__ float  g_x4[(size_t)BATCH * F];   // 128 MB
__device__ float  g_fc0T[F * F];
__device__ float  g_fc1T[F * F];
__device__ float  g_wHiT[HID * F];
__device__ float  g_wLoT[HID * F];
__device__ float  g_fsum[NCLS * F];
__device__ float  g_l1part[32];
__device__ int    g_counts[NCLS];
__device__ double g_s2, g_ce, g_acc;

// ---------------- helpers ----------------
__device__ __forceinline__ uint32_t smem_u32(const void* p) {
    uint32_t a;
    asm("{ .reg .u64 t; cvta.to.shared.u64 t, %1; cvt.u32.u64 %0, t; }"
        : "=r"(a) : "l"(p));
    return a;
}
__device__ __forceinline__ void cpasync16(uint32_t dst, const void* src) {
    asm volatile("cp.async.cg.shared.global [%0], [%1], 16;"
                 :: "r"(dst), "l"(src) : "memory");
}
#define CP_COMMIT() asm volatile("cp.async.commit_group;" ::: "memory")
#define CP_WAIT(n)  asm volatile("cp.async.wait_group %0;" :: "n"(n) : "memory")

__device__ __forceinline__ void ldsm_x4(uint32_t* r, uint32_t addr) {
    asm volatile("ldmatrix.sync.aligned.m8n8.x4.shared.b16 {%0,%1,%2,%3}, [%4];"
                 : "=r"(r[0]), "=r"(r[1]), "=r"(r[2]), "=r"(r[3]) : "r"(addr));
}
__device__ __forceinline__ float tf32_hi(float f) {
    return __uint_as_float(__float_as_uint(f) & 0xFFFFE000u);
}
__device__ __forceinline__ void mma_tf32(float* c, const uint32_t* a, const uint32_t* b) {
    asm volatile("mma.sync.aligned.m16n8k8.row.col.f32.tf32.tf32.f32 "
                 "{%0,%1,%2,%3}, {%4,%5,%6,%7}, {%8,%9}, {%0,%1,%2,%3};"
                 : "+f"(c[0]), "+f"(c[1]), "+f"(c[2]), "+f"(c[3])
                 : "r"(a[0]), "r"(a[1]), "r"(a[2]), "r"(a[3]), "r"(b[0]), "r"(b[1]));
}

// ================= prep: transposes + l1 partials + hist + init =================
// blocks 0-255: fc0/fc1 transpose; 256-383: w hi/lo transpose;
// 384-415: l1 partial (stored, no accumulation); 416: histogram (store-only);
// 417: zero fsum + scalar accumulators.
__global__ __launch_bounds__(1024) void prep_kernel(
    const float* __restrict__ fc0, const float* __restrict__ fc1,
    const float* __restrict__ w, const float* __restrict__ w1,
    const int* __restrict__ y)
{
    __shared__ float t0[32][33];
    __shared__ float t1[32][33];
    __shared__ int   h2[16][12];
    __shared__ float red[32];
    const int b = blockIdx.x;
    const int tid = threadIdx.x;

    if (b < 256) {
        int bx = (b & 15) * 32, by = (b >> 4) * 32;
        int txi = tid & 31, tyi = tid >> 5;
        t0[tyi][txi] = fc0[(by + tyi) * F + bx + txi];
        t1[tyi][txi] = fc1[(by + tyi) * F + bx + txi];
        __syncthreads();
        g_fc0T[(bx + tyi) * F + by + txi] = t0[txi][tyi];
        g_fc1T[(bx + tyi) * F + by + txi] = t1[txi][tyi];
    } else if (b < 384) {
        int bb = b - 256;
        int bx = (bb & 7) * 32, by = (bb >> 3) * 32;
        int txi = tid & 31, tyi = tid >> 5;
        t0[tyi][txi] = w[(by + tyi) * HID + bx + txi];
        __syncthreads();
        float v = t0[txi][tyi];
        float hi = tf32_hi(v);
        size_t o = (size_t)(bx + tyi) * F + by + txi;
        g_wHiT[o] = hi;
        g_wLoT[o] = v - hi;
    } else if (b < 416) {
        float s = 0.f;
        int i0 = (b - 384) * 1024 + tid;
        const int stride = 32 * 1024;
        for (int k = i0; k < F * F; k += stride) s += fabsf(fc0[k]) + fabsf(fc1[k]);
        for (int k = i0; k < F * HID; k += stride) s += fabsf(w[k]);
        for (int k = i0; k < HID * NCLS; k += stride) s += fabsf(w1[k]);
#pragma unroll
        for (int o = 16; o; o >>= 1) s += __shfl_xor_sync(0xffffffffu, s, o);
        if ((tid & 31) == 0) red[tid >> 5] = s;
        __syncthreads();
        if (tid == 0) {
            float t = 0.f;
            for (int i = 0; i < 32; i++) t += red[i];
            g_l1part[b - 384] = t;
        }
    } else if (b == 416) {
        if (tid < 192) ((int*)h2)[tid] = 0;
        __syncthreads();
        int sub = tid & 15;
        for (int i = tid; i < BATCH; i += 1024) atomicAdd(&h2[sub][y[i]], 1);
        __syncthreads();
        if (tid < NCLS) {
            int t = 0;
            for (int s = 0; s < 16; s++) t += h2[s][tid];
            g_counts[tid] = t;
        }
    } else {
        for (int i = tid; i < NCLS * F; i += 1024) g_fsum[i] = 0.f;
        if (tid == 0) { g_s2 = 0.0; g_ce = 0.0; g_acc = 0.0; }
    }
}

// ============ gate: x4 = x + (1+sigmoid(x@fc0))*relu(x@fc1) ============
// CTA: 128 rows x 64 logical cols (both matrices interleaved in B smem).
// 3-stage cp.async pipeline, XOR-swizzled smem, ldmatrix fragment loads.
#define G_STAGE_FL 8192              // A 4096 + B 4096 floats
#define G_CSUM_FL  (3 * G_STAGE_FL)  // 24576
#define G_RED_FL   (G_CSUM_FL + NCLS * 68)
#define GATE_FL    (G_RED_FL + 8)

__global__ __launch_bounds__(256, 2) void gate_kernel(
    const float* __restrict__ x, const int* __restrict__ y)
{
    extern __shared__ float sm[];
    const uint32_t smb = smem_u32(sm);
    float* csum = sm + G_CSUM_FL;
    float* red  = sm + G_RED_FL;

    const int tid = threadIdx.x;
    const int lane = tid & 31, wid = tid >> 5;
    const int g = lane >> 2, tig = lane & 3;
    const int lane7 = lane & 7;
    const int warpM = wid & 3, warpN = wid >> 2;
    const int rowBase = blockIdx.y * 128;
    const int colBase = blockIdx.x * 64;

    // ldmatrix per-lane row offsets
    const int rowoffA = ((lane >> 3) & 1) * 8 + lane7;  // hA = lane>>4
    const int hA = lane >> 4;
    const int rowoffB = ((lane >> 4) & 1) * 8 + lane7;  // hB = (lane>>3)&1
    const int hB = (lane >> 3) & 1;

    for (int i = tid; i < NCLS * 68; i += 256) csum[i] = 0.f;

    float acc[2][8][4];
#pragma unroll
    for (int mt = 0; mt < 2; mt++)
#pragma unroll
        for (int nt = 0; nt < 8; nt++)
#pragma unroll
            for (int r = 0; r < 4; r++) acc[mt][nt][r] = 0.f;

    auto issue = [&](int ch) {
        const int p = ch % 3;
        const uint32_t sA = smb + p * (G_STAGE_FL * 4);
        const uint32_t sB = sA + 16384;
        const int kb = ch * 32;
#pragma unroll
        for (int l = 0; l < 4; l++) {
            int idx = l * 256 + tid;
            int r = idx >> 3, q = idx & 7;
            cpasync16(sA + (r * 8 + (q ^ (r & 7))) * 16,
                      &x[(size_t)(rowBase + r) * F + kb + q * 4]);
        }
#pragma unroll
        for (int l = 0; l < 4; l++) {
            int idx = l * 256 + tid;
            int nb = idx >> 3, q = idx & 7;
            int m = (nb >> 3) & 1;
            int L = ((nb >> 4) << 3) | (nb & 7);
            const float* src = (m ? g_fc1T : g_fc0T)
                             + (size_t)(colBase + L) * F + kb + q * 4;
            cpasync16(sB + (nb * 8 + (q ^ (nb & 7))) * 16, src);
        }
        CP_COMMIT();
    };

    issue(0);
    issue(1);

    for (int ch = 0; ch < 16; ch++) {
        if (ch < 14) issue(ch + 2); else CP_COMMIT();
        CP_WAIT(2);
        __syncthreads();

        const uint32_t stBase = smb + (ch % 3) * (G_STAGE_FL * 4);
        const uint32_t aB0 = stBase + (uint32_t)(warpM * 32 + rowoffA) * 128;
        const uint32_t bB  = stBase + 16384;
        uint32_t bAddr[4];
#pragma unroll
        for (int gi = 0; gi < 4; gi++)
            bAddr[gi] = bB + (uint32_t)(warpN * 64 + gi * 16 + rowoffB) * 128;

#pragma unroll
        for (int s = 0; s < 4; s++) {
            const uint32_t offA = (uint32_t)(((2 * s + hA) ^ lane7) << 4);
            const uint32_t offB = (uint32_t)(((2 * s + hB) ^ lane7) << 4);
            uint32_t a[2][4];
            ldsm_x4(a[0], aB0 + offA);
            ldsm_x4(a[1], aB0 + 2048 + offA);  // +16 rows * 128B
            uint32_t bq[4][4];
#pragma unroll
            for (int gi = 0; gi < 4; gi++) ldsm_x4(bq[gi], bAddr[gi] + offB);
#pragma unroll
            for (int mt = 0; mt < 2; mt++)
#pragma unroll
                for (int gi = 0; gi < 4; gi++) {
                    mma_tf32(acc[mt][2 * gi],     a[mt], &bq[gi][0]);
                    mma_tf32(acc[mt][2 * gi + 1], a[mt], &bq[gi][2]);
                }
        }
        __syncthreads();
    }

    // ---- epilogue ----
    float s2loc = 0.f;
#pragma unroll
    for (int mt = 0; mt < 2; mt++) {
        int r0 = rowBase + warpM * 32 + mt * 16 + g;
        int r1 = r0 + 8;
        int y0 = y[r0], y1 = y[r1];
#pragma unroll
        for (int j = 0; j < 4; j++) {
            int lcol = warpN * 32 + j * 8 + 2 * tig;
            int gcol = colBase + lcol;
            {
                float A0x = acc[mt][2 * j][0], A0y = acc[mt][2 * j][1];
                float A1x = acc[mt][2 * j + 1][0], A1y = acc[mt][2 * j + 1][1];
                float2 xv = *(const float2*)&x[(size_t)r0 * F + gcol];
                float ox = xv.x + (1.f + 1.f / (1.f + expf(-A0x))) * fmaxf(A1x, 0.f);
                float oy = xv.y + (1.f + 1.f / (1.f + expf(-A0y))) * fmaxf(A1y, 0.f);
                *(float2*)&g_x4[(size_t)r0 * F + gcol] = make_float2(ox, oy);
                s2loc += ox * ox + oy * oy;
                atomicAdd(&csum[y0 * 68 + lcol], ox);
                atomicAdd(&csum[y0 * 68 + lcol + 1], oy);
            }
            {
                float A0x = acc[mt][2 * j][2], A0y = acc[mt][2 * j][3];
                float A1x = acc[mt][2 * j + 1][2], A1y = acc[mt][2 * j + 1][3];
                float2 xv = *(const float2*)&x[(size_t)r1 * F + gcol];
                float ox = xv.x + (1.f + 1.f / (1.f + expf(-A0x))) * fmaxf(A1x, 0.f);
                float oy = xv.y + (1.f + 1.f / (1.f + expf(-A0y))) * fmaxf(A1y, 0.f);
                *(float2*)&g_x4[(size_t)r1 * F + gcol] = make_float2(ox, oy);
                s2loc += ox * ox + oy * oy;
                atomicAdd(&csum[y1 * 68 + lcol], ox);
                atomicAdd(&csum[y1 * 68 + lcol + 1], oy);
            }
        }
    }
    __syncthreads();

    for (int i = tid; i < NCLS * 64; i += 256) {
        int c = i >> 6, col = i & 63;
        float v = csum[c * 68 + col];
        if (v != 0.f) atomicAdd(&g_fsum[c * F + colBase + col], v);
    }
#pragma unroll
    for (int o = 16; o; o >>= 1) s2loc += __shfl_xor_sync(0xffffffffu, s2loc, o);
    if (lane == 0) red[wid] = s2loc;
    __syncthreads();
    if (tid == 0) {
        float t = 0.f;
        for (int i = 0; i < 8; i++) t += red[i];
        atomicAdd(&g_s2, (double)t);
    }
}

// ============ head: logits = relu(x4@w)@w1, 3-term tf32 split, BM=128 ============
// CTA: 128 rows x 256 cols; 8 warps as 2(M) x 4(N). 2-stage cp.async pipeline.
#define H_STAGE_FL 20480   // Araw 4096 + WH 8192 + WL 8192
#define H_W1_FL    (2 * H_STAGE_FL)           // 40960
#define H_PART_FL  (H_W1_FL + NCLS * 260)     // 43560
#define H_LOG_FL   (H_PART_FL + 4 * 128 * NCLS)  // 48680
#define HEAD_FL    (H_LOG_FL + 128 * NCLS)    // 49960 floats = 199840 B

__global__ __launch_bounds__(256, 1) void head_kernel(
    const float* __restrict__ w1, const int* __restrict__ y)
{
    extern __shared__ float sm[];
    const uint32_t smb = smem_u32(sm);
    float* w1t    = sm + H_W1_FL;
    float* part   = sm + H_PART_FL;
    float* logits = sm + H_LOG_FL;

    const int tid = threadIdx.x;
    const int lane = tid & 31, wid = tid >> 5;
    const int g = lane >> 2, tig = lane & 3;
    const int lane7 = lane & 7;
    const int warpM = wid >> 2, warpN = wid & 3;
    const int rowBase = blockIdx.x * 128;

    const int rowoffA = ((lane >> 3) & 1) * 8 + lane7;
    const int hA = lane >> 4;
    const int rowoffB = ((lane >> 4) & 1) * 8 + lane7;
    const int hB = (lane >> 3) & 1;

    for (int i = tid; i < HID * NCLS; i += 256) {
        int jj = i / NCLS, c = i % NCLS;
        w1t[c * 260 + jj] = w1[i];
    }

    float acc[128];
#pragma unroll
    for (int i = 0; i < 128; i++) acc[i] = 0.f;

    auto issue = [&](int ch) {
        const int p = ch & 1;
        const uint32_t sA = smb + p * (H_STAGE_FL * 4);
        const uint32_t sH = sA + 4096 * 4;
        const uint32_t sL = sH + 8192 * 4;
        const int kb = ch * 32;
#pragma unroll
        for (int l = 0; l < 4; l++) {
            int idx = l * 256 + tid;
            int r = idx >> 3, q = idx & 7;
            cpasync16(sA + (r * 8 + (q ^ (r & 7))) * 16,
                      &g_x4[(size_t)(rowBase + r) * F + kb + q * 4]);
        }
#pragma unroll
        for (int l = 0; l < 8; l++) {
            int idx = l * 256 + tid;
            int nb = idx >> 3, q = idx & 7;
            uint32_t so = (nb * 8 + (q ^ (nb & 7))) * 16;
            cpasync16(sH + so, &g_wHiT[(size_t)nb * F + kb + q * 4]);
            cpasync16(sL + so, &g_wLoT[(size_t)nb * F + kb + q * 4]);
        }
        CP_COMMIT();
    };

    issue(0);

    for (int ch = 0; ch < 16; ch++) {
        if (ch < 15) issue(ch + 1); else CP_COMMIT();
        CP_WAIT(1);
        __syncthreads();

        const uint32_t sA = smb + (ch & 1) * (H_STAGE_FL * 4);
        const uint32_t aB0 = sA + (uint32_t)(warpM * 64 + rowoffA) * 128;
        const uint32_t sH = sA + 4096 * 4;
        const uint32_t sL = sH + 8192 * 4;
        uint32_t whAddr[4], wlAddr[4];
#pragma unroll
        for (int gi = 0; gi < 4; gi++) {
            uint32_t ro = (uint32_t)(warpN * 64 + gi * 16 + rowoffB) * 128;
            whAddr[gi] = sH + ro;
            wlAddr[gi] = sL + ro;
        }

#pragma unroll
        for (int s = 0; s < 4; s++) {
            const uint32_t offA = (uint32_t)(((2 * s + hA) ^ lane7) << 4);
            const uint32_t offB = (uint32_t)(((2 * s + hB) ^ lane7) << 4);
            uint32_t ah[4][4], al[4][4];
#pragma unroll
            for (int mt = 0; mt < 4; mt++) {
                uint32_t raw[4];
                ldsm_x4(raw, aB0 + (uint32_t)(mt * 16) * 128 + offA);
#pragma unroll
                for (int e = 0; e < 4; e++) {
                    uint32_t hbits = raw[e] & 0xFFFFE000u;
                    ah[mt][e] = hbits;
                    al[mt][e] = __float_as_uint(
                        __uint_as_float(raw[e]) - __uint_as_float(hbits));
                }
            }
#pragma unroll
            for (int gi = 0; gi < 4; gi++) {
                uint32_t bh[4], bl[4];
                ldsm_x4(bh, whAddr[gi] + offB);
                ldsm_x4(bl, wlAddr[gi] + offB);
#pragma unroll
                for (int j = 0; j < 2; j++) {
                    const int nt = 2 * gi + j;
#pragma unroll
                    for (int mt = 0; mt < 4; mt++) {
                        float* c = &acc[(mt * 8 + nt) * 4];
                        mma_tf32(c, al[mt], &bh[2 * j]);
                        mma_tf32(c, ah[mt], &bl[2 * j]);
                        mma_tf32(c, ah[mt], &bh[2 * j]);
                    }
                }
            }
        }
        __syncthreads();
    }

    // relu
#pragma unroll
    for (int i = 0; i < 128; i++) acc[i] = fmaxf(acc[i], 0.f);

    // partial logits per warp (its 64-col slice), quad-reduced
#pragma unroll
    for (int c = 0; c < NCLS; c++) {
        float w1v[16];
#pragma unroll
        for (int nt = 0; nt < 8; nt++) {
            int col = warpN * 64 + nt * 8 + 2 * tig;
            w1v[nt * 2]     = w1t[c * 260 + col];
            w1v[nt * 2 + 1] = w1t[c * 260 + col + 1];
        }
#pragma unroll
        for (int mt = 0; mt < 4; mt++)
#pragma unroll
            for (int rr = 0; rr < 2; rr++) {
                float s = 0.f;
#pragma unroll
                for (int nt = 0; nt < 8; nt++) {
                    s += acc[(mt * 8 + nt) * 4 + rr * 2]     * w1v[nt * 2];
                    s += acc[(mt * 8 + nt) * 4 + rr * 2 + 1] * w1v[nt * 2 + 1];
                }
                s += __shfl_xor_sync(0xffffffffu, s, 1);
                s += __shfl_xor_sync(0xffffffffu, s, 2);
                if (tig == 0) {
                    int row = warpM * 64 + mt * 16 + g + rr * 8;
                    part[warpN * (128 * NCLS) + row * NCLS + c] = s;
                }
            }
    }
    __syncthreads();

    for (int i = tid; i < 128 * NCLS; i += 256) {
        float t = part[i] + part[128 * NCLS + i]
                + part[2 * 128 * NCLS + i] + part[3 * 128 * NCLS + i];
        logits[i] = t;
    }
    __syncthreads();

    if (tid < 128) {
        int row = rowBase + tid;
        int yr = y[row];
        const float* lg = &logits[tid * NCLS];
        float m = lg[0]; int bi = 0;
#pragma unroll
        for (int c = 1; c < NCLS; c++) if (lg[c] > m) { m = lg[c]; bi = c; }
        float se = 0.f;
#pragma unroll
        for (int c = 0; c < NCLS; c++) se += expf(lg[c] - m);
        float ce_loc = (m + logf(se)) - lg[yr];
        float corr_loc = (bi == yr) ? 1.f : 0.f;
#pragma unroll
        for (int o = 16; o; o >>= 1) {
            ce_loc += __shfl_xor_sync(0xffffffffu, ce_loc, o);
            corr_loc += __shfl_xor_sync(0xffffffffu, corr_loc, o);
        }
        if ((tid & 31) == 0) {
            atomicAdd(&g_ce, (double)ce_loc);
            atomicAdd(&g_acc, (double)corr_loc);
        }
    }
}

// ---------------- finalize ----------------
__global__ void final_kernel(float* __restrict__ out) {
    int tid = threadIdx.x;
    float t = 0.f;
    for (int i = tid; i < NCLS * F; i += 256) {
        int c = i / F;
        int cnt = g_counts[c]; if (cnt < 1) cnt = 1;
        float v = g_fsum[i];
        t += v * v / (float)cnt;
    }
#pragma unroll
    for (int o = 16; o; o >>= 1) t += __shfl_xor_sync(0xffffffffu, t, o);
    __shared__ float red[8];
    if ((tid & 31) == 0) red[tid >> 5] = t;
    __syncthreads();
    if (tid == 0) {
        double tt = 0.0;
        for (int i = 0; i < 8; i++) tt += (double)red[i];
        double l1 = 0.0;
        for (int i = 0; i < 32; i++) l1 += (double)g_l1part[i];
        double var = g_s2 - tt;
        double loss = g_ce / (double)BATCH + 1e-4 * l1 + 1e-3 * var;
        out[0] = (float)loss;
        out[1] = (float)(g_acc / (double)BATCH);
    }
}

// ---------------- launch ----------------
extern "C" void kernel_launch(void* const* d_in, const int* in_sizes, int n_in,
                              void* d_out, int out_size) {
    const float* x   = (const float*)d_in[0];
    const int*   y   = (const int*)d_in[1];
    const float* fc0 = (const float*)d_in[2];
    const float* fc1 = (const float*)d_in[3];
    const float* w   = (const float*)d_in[4];
    const float* w1  = (const float*)d_in[5];
    float* out = (float*)d_out;

    static int configured = 0;
    if (!configured) {
        cudaFuncSetAttribute(gate_kernel, cudaFuncAttributeMaxDynamicSharedMemorySize,
                             GATE_FL * 4);
        cudaFuncSetAttribute(head_kernel, cudaFuncAttributeMaxDynamicSharedMemorySize,
                             HEAD_FL * 4);
        configured = 1;
    }

    prep_kernel<<<418, 1024>>>(fc0, fc1, w, w1, y);
    gate_kernel<<<dim3(F / 64, BATCH / 128), 256, GATE_FL * 4>>>(x, y);
    head_kernel<<<BATCH / 128, 256, HEAD_FL * 4>>>(w1, y);
    final_kernel<<<1, 256>>>(out);
}

// round 6
// speedup vs baseline: 3.4448x; 1.1611x over previous
#include <cuda_runtime.h>
#include <cuda_bf16.h>
#include <math.h>
#include <stdint.h>

#define BATCH 65536
#define F     512
#define HID   256
#define NCLS  10

// ---------------- scratch ----------------
__device__ __align__(16) unsigned short g_x4h[(size_t)BATCH * F];  // 64 MB
__device__ __align__(16) unsigned short g_x4l[(size_t)BATCH * F];  // 64 MB
__device__ float  g_fc0T[F * F];
__device__ float  g_fc1T[F * F];
__device__ __align__(16) unsigned short g_wHiB[HID * F];
__device__ __align__(16) unsigned short g_wLoB[HID * F];
__device__ float  g_fsum[NCLS * F];
__device__ float  g_l1part[32];
__device__ int    g_counts[NCLS];
__device__ double g_s2, g_ce, g_acc;

// ---------------- helpers ----------------
__device__ __forceinline__ uint32_t smem_u32(const void* p) {
    uint32_t a;
    asm("{ .reg .u64 t; cvta.to.shared.u64 t, %1; cvt.u32.u64 %0, t; }"
        : "=r"(a) : "l"(p));
    return a;
}
__device__ __forceinline__ void cpasync16(uint32_t dst, const void* src) {
    asm volatile("cp.async.cg.shared.global [%0], [%1], 16;"
                 :: "r"(dst), "l"(src) : "memory");
}
#define CP_COMMIT() asm volatile("cp.async.commit_group;" ::: "memory")
#define CP_WAIT(n)  asm volatile("cp.async.wait_group %0;" :: "n"(n) : "memory")

__device__ __forceinline__ void ldsm_x4(uint32_t* r, uint32_t addr) {
    asm volatile("ldmatrix.sync.aligned.m8n8.x4.shared.b16 {%0,%1,%2,%3}, [%4];"
                 : "=r"(r[0]), "=r"(r[1]), "=r"(r[2]), "=r"(r[3]) : "r"(addr));
}
__device__ __forceinline__ float tf32_hi(float f) {
    return __uint_as_float(__float_as_uint(f) & 0xFFFFE000u);
}
__device__ __forceinline__ void mma_tf32(float* c, const uint32_t* a, const uint32_t* b) {
    asm volatile("mma.sync.aligned.m16n8k8.row.col.f32.tf32.tf32.f32 "
                 "{%0,%1,%2,%3}, {%4,%5,%6,%7}, {%8,%9}, {%0,%1,%2,%3};"
                 : "+f"(c[0]), "+f"(c[1]), "+f"(c[2]), "+f"(c[3])
                 : "r"(a[0]), "r"(a[1]), "r"(a[2]), "r"(a[3]), "r"(b[0]), "r"(b[1]));
}
__device__ __forceinline__ void mma_bf16(float* c, const uint32_t* a, const uint32_t* b) {
    asm volatile("mma.sync.aligned.m16n8k16.row.col.f32.bf16.bf16.f32 "
                 "{%0,%1,%2,%3}, {%4,%5,%6,%7}, {%8,%9}, {%0,%1,%2,%3};"
                 : "+f"(c[0]), "+f"(c[1]), "+f"(c[2]), "+f"(c[3])
                 : "r"(a[0]), "r"(a[1]), "r"(a[2]), "r"(a[3]), "r"(b[0]), "r"(b[1]));
}

// ================= prep: transposes + l1 partials + hist + init =================
__global__ __launch_bounds__(1024) void prep_kernel(
    const float* __restrict__ fc0, const float* __restrict__ fc1,
    const float* __restrict__ w, const float* __restrict__ w1,
    const int* __restrict__ y)
{
    __shared__ float t0[32][33];
    __shared__ float t1[32][33];
    __shared__ int   h2[16][12];
    __shared__ float red[32];
    const int b = blockIdx.x;
    const int tid = threadIdx.x;

    if (b < 256) {
        int bx = (b & 15) * 32, by = (b >> 4) * 32;
        int txi = tid & 31, tyi = tid >> 5;
        t0[tyi][txi] = fc0[(by + tyi) * F + bx + txi];
        t1[tyi][txi] = fc1[(by + tyi) * F + bx + txi];
        __syncthreads();
        g_fc0T[(bx + tyi) * F + by + txi] = t0[txi][tyi];
        g_fc1T[(bx + tyi) * F + by + txi] = t1[txi][tyi];
    } else if (b < 384) {
        int bb = b - 256;
        int bx = (bb & 7) * 32, by = (bb >> 3) * 32;
        int txi = tid & 31, tyi = tid >> 5;
        t0[tyi][txi] = w[(by + tyi) * HID + bx + txi];
        __syncthreads();
        float v = t0[txi][tyi];
        __nv_bfloat16 hb = __float2bfloat16(v);
        float hf = __bfloat162float(hb);
        __nv_bfloat16 lb = __float2bfloat16(v - hf);
        size_t o = (size_t)(bx + tyi) * F + by + txi;
        g_wHiB[o] = *(unsigned short*)&hb;
        g_wLoB[o] = *(unsigned short*)&lb;
    } else if (b < 416) {
        float s = 0.f;
        int i0 = (b - 384) * 1024 + tid;
        const int stride = 32 * 1024;
        for (int k = i0; k < F * F; k += stride) s += fabsf(fc0[k]) + fabsf(fc1[k]);
        for (int k = i0; k < F * HID; k += stride) s += fabsf(w[k]);
        for (int k = i0; k < HID * NCLS; k += stride) s += fabsf(w1[k]);
#pragma unroll
        for (int o = 16; o; o >>= 1) s += __shfl_xor_sync(0xffffffffu, s, o);
        if ((tid & 31) == 0) red[tid >> 5] = s;
        __syncthreads();
        if (tid == 0) {
            float t = 0.f;
            for (int i = 0; i < 32; i++) t += red[i];
            g_l1part[b - 384] = t;
        }
    } else if (b == 416) {
        if (tid < 192) ((int*)h2)[tid] = 0;
        __syncthreads();
        int sub = tid & 15;
        for (int i = tid; i < BATCH; i += 1024) atomicAdd(&h2[sub][y[i]], 1);
        __syncthreads();
        if (tid < NCLS) {
            int t = 0;
            for (int s = 0; s < 16; s++) t += h2[s][tid];
            g_counts[tid] = t;
        }
    } else {
        for (int i = tid; i < NCLS * F; i += 1024) g_fsum[i] = 0.f;
        if (tid == 0) { g_s2 = 0.0; g_ce = 0.0; g_acc = 0.0; }
    }
}

// ============ gate: x4 = x + (1+sigmoid(x@fc0))*relu(x@fc1) ============
#define G_STAGE_FL 8192
#define G_CSUM_FL  (3 * G_STAGE_FL)
#define G_RED_FL   (G_CSUM_FL + NCLS * 68)
#define GATE_FL    (G_RED_FL + 8)

__global__ __launch_bounds__(256, 2) void gate_kernel(
    const float* __restrict__ x, const int* __restrict__ y)
{
    extern __shared__ float sm[];
    const uint32_t smb = smem_u32(sm);
    float* csum = sm + G_CSUM_FL;
    float* red  = sm + G_RED_FL;

    const int tid = threadIdx.x;
    const int lane = tid & 31, wid = tid >> 5;
    const int g = lane >> 2, tig = lane & 3;
    const int lane7 = lane & 7;
    const int warpM = wid & 3, warpN = wid >> 2;
    const int rowBase = blockIdx.y * 128;
    const int colBase = blockIdx.x * 64;

    const int rowoffA = ((lane >> 3) & 1) * 8 + lane7;
    const int hA = lane >> 4;
    const int rowoffB = ((lane >> 4) & 1) * 8 + lane7;
    const int hB = (lane >> 3) & 1;

    for (int i = tid; i < NCLS * 68; i += 256) csum[i] = 0.f;

    float acc[2][8][4];
#pragma unroll
    for (int mt = 0; mt < 2; mt++)
#pragma unroll
        for (int nt = 0; nt < 8; nt++)
#pragma unroll
            for (int r = 0; r < 4; r++) acc[mt][nt][r] = 0.f;

    auto issue = [&](int ch) {
        const int p = ch % 3;
        const uint32_t sA = smb + p * (G_STAGE_FL * 4);
        const uint32_t sB = sA + 16384;
        const int kb = ch * 32;
#pragma unroll
        for (int l = 0; l < 4; l++) {
            int idx = l * 256 + tid;
            int r = idx >> 3, q = idx & 7;
            cpasync16(sA + (r * 8 + (q ^ (r & 7))) * 16,
                      &x[(size_t)(rowBase + r) * F + kb + q * 4]);
        }
#pragma unroll
        for (int l = 0; l < 4; l++) {
            int idx = l * 256 + tid;
            int nb = idx >> 3, q = idx & 7;
            int m = (nb >> 3) & 1;
            int L = ((nb >> 4) << 3) | (nb & 7);
            const float* src = (m ? g_fc1T : g_fc0T)
                             + (size_t)(colBase + L) * F + kb + q * 4;
            cpasync16(sB + (nb * 8 + (q ^ (nb & 7))) * 16, src);
        }
        CP_COMMIT();
    };

    issue(0);
    issue(1);

    for (int ch = 0; ch < 16; ch++) {
        if (ch < 14) issue(ch + 2); else CP_COMMIT();
        CP_WAIT(2);
        __syncthreads();

        const uint32_t stBase = smb + (ch % 3) * (G_STAGE_FL * 4);
        const uint32_t aB0 = stBase + (uint32_t)(warpM * 32 + rowoffA) * 128;
        const uint32_t bB  = stBase + 16384;
        uint32_t bAddr[4];
#pragma unroll
        for (int gi = 0; gi < 4; gi++)
            bAddr[gi] = bB + (uint32_t)(warpN * 64 + gi * 16 + rowoffB) * 128;

#pragma unroll
        for (int s = 0; s < 4; s++) {
            const uint32_t offA = (uint32_t)(((2 * s + hA) ^ lane7) << 4);
            const uint32_t offB = (uint32_t)(((2 * s + hB) ^ lane7) << 4);
            uint32_t a[2][4];
            ldsm_x4(a[0], aB0 + offA);
            ldsm_x4(a[1], aB0 + 2048 + offA);
            uint32_t bq[4][4];
#pragma unroll
            for (int gi = 0; gi < 4; gi++) ldsm_x4(bq[gi], bAddr[gi] + offB);
#pragma unroll
            for (int mt = 0; mt < 2; mt++)
#pragma unroll
                for (int gi = 0; gi < 4; gi++) {
                    mma_tf32(acc[mt][2 * gi],     a[mt], &bq[gi][0]);
                    mma_tf32(acc[mt][2 * gi + 1], a[mt], &bq[gi][2]);
                }
        }
        __syncthreads();
    }

    // ---- epilogue: x4 -> bf16 hi/lo split, s2, class sums ----
    float s2loc = 0.f;
#pragma unroll
    for (int mt = 0; mt < 2; mt++) {
        int r0 = rowBase + warpM * 32 + mt * 16 + g;
        int r1 = r0 + 8;
        int y0 = y[r0], y1 = y[r1];
#pragma unroll
        for (int j = 0; j < 4; j++) {
            int lcol = warpN * 32 + j * 8 + 2 * tig;
            int gcol = colBase + lcol;
#pragma unroll
            for (int rr = 0; rr < 2; rr++) {
                int row = rr ? r1 : r0;
                int yr = rr ? y1 : y0;
                float A0x = acc[mt][2 * j][rr * 2],     A0y = acc[mt][2 * j][rr * 2 + 1];
                float A1x = acc[mt][2 * j + 1][rr * 2], A1y = acc[mt][2 * j + 1][rr * 2 + 1];
                float2 xv = *(const float2*)&x[(size_t)row * F + gcol];
                float ox = xv.x + (1.f + 1.f / (1.f + expf(-A0x))) * fmaxf(A1x, 0.f);
                float oy = xv.y + (1.f + 1.f / (1.f + expf(-A0y))) * fmaxf(A1y, 0.f);
                __nv_bfloat162 hv = __floats2bfloat162_rn(ox, oy);
                *(uint32_t*)&g_x4h[(size_t)row * F + gcol] = *(uint32_t*)&hv;
                float lx = ox - __bfloat162float(hv.x);
                float ly = oy - __bfloat162float(hv.y);
                __nv_bfloat162 lv = __floats2bfloat162_rn(lx, ly);
                *(uint32_t*)&g_x4l[(size_t)row * F + gcol] = *(uint32_t*)&lv;
                s2loc += ox * ox + oy * oy;
                atomicAdd(&csum[yr * 68 + lcol], ox);
                atomicAdd(&csum[yr * 68 + lcol + 1], oy);
            }
        }
    }
    __syncthreads();

    for (int i = tid; i < NCLS * 64; i += 256) {
        int c = i >> 6, col = i & 63;
        float v = csum[c * 68 + col];
        if (v != 0.f) atomicAdd(&g_fsum[c * F + colBase + col], v);
    }
#pragma unroll
    for (int o = 16; o; o >>= 1) s2loc += __shfl_xor_sync(0xffffffffu, s2loc, o);
    if (lane == 0) red[wid] = s2loc;
    __syncthreads();
    if (tid == 0) {
        float t = 0.f;
        for (int i = 0; i < 8; i++) t += red[i];
        atomicAdd(&g_s2, (double)t);
    }
}

// ============ head: logits = relu(x4@w)@w1, 3-term bf16 split, k16 mma ============
// CTA: 128 rows x 256 cols; 8 warps as 2(M) x 4(N). 2-stage cp.async pipeline.
// Stage (48 KB): Ahi[128][32]bf16 8K | Alo 8K | Whi[256][32]bf16 16K | Wlo 16K.
// smem row = 64 B; swizzle: addr(row,gran) = row*64 + ((gran ^ ((row>>1)&3))<<4).
#define H_STAGE_B  49152
#define H_W1_FL    24576                       // after 2 stages (98304 B)
#define H_PART_FL  (H_W1_FL + NCLS * 260)
#define H_LOG_FL   (H_PART_FL + 4 * 128 * NCLS)
#define HEAD_FL    (H_LOG_FL + 128 * NCLS)

__global__ __launch_bounds__(256, 1) void head_kernel(
    const float* __restrict__ w1, const int* __restrict__ y)
{
    extern __shared__ float sm[];
    const uint32_t smb = smem_u32(sm);
    float* w1t    = sm + H_W1_FL;
    float* part   = sm + H_PART_FL;
    float* logits = sm + H_LOG_FL;

    const int tid = threadIdx.x;
    const int lane = tid & 31, wid = tid >> 5;
    const int g = lane >> 2, tig = lane & 3;
    const int warpM = wid >> 2, warpN = wid & 3;
    const int rowBase = blockIdx.x * 128;

    for (int i = tid; i < HID * NCLS; i += 256) {
        int jj = i / NCLS, c = i % NCLS;
        w1t[c * 260 + jj] = w1[i];
    }

    float acc[128];
#pragma unroll
    for (int i = 0; i < 128; i++) acc[i] = 0.f;

    auto issue = [&](int ch) {
        const uint32_t sBase = smb + (ch & 1) * H_STAGE_B;
        const int kb = ch * 32;
        // A hi/lo: 512 granules each
#pragma unroll
        for (int l = 0; l < 2; l++) {
            int idx = l * 256 + tid;
            int r = idx >> 2, q = idx & 3;
            uint32_t so = (uint32_t)r * 64 + (uint32_t)((q ^ ((r >> 1) & 3)) << 4);
            size_t go = (size_t)(rowBase + r) * F + kb + q * 8;
            cpasync16(sBase + so, &g_x4h[go]);
            cpasync16(sBase + 8192 + so, &g_x4l[go]);
        }
        // W hi/lo: 1024 granules each
#pragma unroll
        for (int l = 0; l < 4; l++) {
            int idx = l * 256 + tid;
            int n = idx >> 2, q = idx & 3;
            uint32_t so = (uint32_t)n * 64 + (uint32_t)((q ^ ((n >> 1) & 3)) << 4);
            size_t go = (size_t)n * F + kb + q * 8;
            cpasync16(sBase + 16384 + so, &g_wHiB[go]);
            cpasync16(sBase + 32768 + so, &g_wLoB[go]);
        }
        CP_COMMIT();
    };

    issue(0);

    const int rA = lane & 15;                                  // A local row
    const int rW = (lane & 7) + ((lane >> 4) << 3);            // W local row
    const int gAsel = lane >> 4;                               // A gran select
    const int gWsel = (lane >> 3) & 1;                         // W gran select

    for (int ch = 0; ch < 16; ch++) {
        if (ch < 15) issue(ch + 1); else CP_COMMIT();
        CP_WAIT(1);
        __syncthreads();

        const uint32_t sBase = smb + (ch & 1) * H_STAGE_B;
#pragma unroll
        for (int s = 0; s < 2; s++) {
            const int granA = 2 * s + gAsel;
            const int granW = 2 * s + gWsel;
            uint32_t ah[4][4], al[4][4];
#pragma unroll
            for (int mt = 0; mt < 4; mt++) {
                int row = warpM * 64 + mt * 16 + rA;
                uint32_t off = (uint32_t)row * 64
                             + (uint32_t)((granA ^ ((row >> 1) & 3)) << 4);
                ldsm_x4(ah[mt], sBase + off);
                ldsm_x4(al[mt], sBase + 8192 + off);
            }
#pragma unroll
            for (int gi = 0; gi < 4; gi++) {
                int nrow = warpN * 64 + gi * 16 + rW;
                uint32_t off = (uint32_t)nrow * 64
                             + (uint32_t)((granW ^ ((nrow >> 1) & 3)) << 4);
                uint32_t bh[4], bl[4];
                ldsm_x4(bh, sBase + 16384 + off);
                ldsm_x4(bl, sBase + 32768 + off);
#pragma unroll
                for (int j = 0; j < 2; j++) {
                    const int nt = 2 * gi + j;
#pragma unroll
                    for (int mt = 0; mt < 4; mt++) {
                        float* c = &acc[(mt * 8 + nt) * 4];
                        mma_bf16(c, al[mt], &bh[2 * j]);
                        mma_bf16(c, ah[mt], &bl[2 * j]);
                        mma_bf16(c, ah[mt], &bh[2 * j]);
                    }
                }
            }
        }
        __syncthreads();
    }

    // relu
#pragma unroll
    for (int i = 0; i < 128; i++) acc[i] = fmaxf(acc[i], 0.f);

    // partial logits per warp, quad-reduced
#pragma unroll
    for (int c = 0; c < NCLS; c++) {
        float w1v[16];
#pragma unroll
        for (int nt = 0; nt < 8; nt++) {
            int col = warpN * 64 + nt * 8 + 2 * tig;
            w1v[nt * 2]     = w1t[c * 260 + col];
            w1v[nt * 2 + 1] = w1t[c * 260 + col + 1];
        }
#pragma unroll
        for (int mt = 0; mt < 4; mt++)
#pragma unroll
            for (int rr = 0; rr < 2; rr++) {
                float s = 0.f;
#pragma unroll
                for (int nt = 0; nt < 8; nt++) {
                    s += acc[(mt * 8 + nt) * 4 + rr * 2]     * w1v[nt * 2];
                    s += acc[(mt * 8 + nt) * 4 + rr * 2 + 1] * w1v[nt * 2 + 1];
                }
                s += __shfl_xor_sync(0xffffffffu, s, 1);
                s += __shfl_xor_sync(0xffffffffu, s, 2);
                if (tig == 0) {
                    int row = warpM * 64 + mt * 16 + g + rr * 8;
                    part[warpN * (128 * NCLS) + row * NCLS + c] = s;
                }
            }
    }
    __syncthreads();

    for (int i = tid; i < 128 * NCLS; i += 256) {
        float t = part[i] + part[128 * NCLS + i]
                + part[2 * 128 * NCLS + i] + part[3 * 128 * NCLS + i];
        logits[i] = t;
    }
    __syncthreads();

    if (tid < 128) {
        int row = rowBase + tid;
        int yr = y[row];
        const float* lg = &logits[tid * NCLS];
        float m = lg[0]; int bi = 0;
#pragma unroll
        for (int c = 1; c < NCLS; c++) if (lg[c] > m) { m = lg[c]; bi = c; }
        float se = 0.f;
#pragma unroll
        for (int c = 0; c < NCLS; c++) se += expf(lg[c] - m);
        float ce_loc = (m + logf(se)) - lg[yr];
        float corr_loc = (bi == yr) ? 1.f : 0.f;
#pragma unroll
        for (int o = 16; o; o >>= 1) {
            ce_loc += __shfl_xor_sync(0xffffffffu, ce_loc, o);
            corr_loc += __shfl_xor_sync(0xffffffffu, corr_loc, o);
        }
        if ((tid & 31) == 0) {
            atomicAdd(&g_ce, (double)ce_loc);
            atomicAdd(&g_acc, (double)corr_loc);
        }
    }
}

// ---------------- finalize ----------------
__global__ __launch_bounds__(1024) void final_kernel(float* __restrict__ out) {
    int tid = threadIdx.x;
    float t = 0.f;
    for (int i = tid; i < NCLS * F; i += 1024) {
        int c = i / F;
        int cnt = g_counts[c]; if (cnt < 1) cnt = 1;
        float v = g_fsum[i];
        t += v * v / (float)cnt;
    }
#pragma unroll
    for (int o = 16; o; o >>= 1) t += __shfl_xor_sync(0xffffffffu, t, o);
    __shared__ float red[32];
    if ((tid & 31) == 0) red[tid >> 5] = t;
    __syncthreads();
    if (tid == 0) {
        double tt = 0.0;
        for (int i = 0; i < 32; i++) tt += (double)red[i];
        double l1 = 0.0;
        for (int i = 0; i < 32; i++) l1 += (double)g_l1part[i];
        double var = g_s2 - tt;
        double loss = g_ce / (double)BATCH + 1e-4 * l1 + 1e-3 * var;
        out[0] = (float)loss;
        out[1] = (float)(g_acc / (double)BATCH);
    }
}

// ---------------- launch ----------------
extern "C" void kernel_launch(void* const* d_in, const int* in_sizes, int n_in,
                              void* d_out, int out_size) {
    const float* x   = (const float*)d_in[0];
    const int*   y   = (const int*)d_in[1];
    const float* fc0 = (const float*)d_in[2];
    const float* fc1 = (const float*)d_in[3];
    const float* w   = (const float*)d_in[4];
    const float* w1  = (const float*)d_in[5];
    float* out = (float*)d_out;

    static int configured = 0;
    if (!configured) {
        cudaFuncSetAttribute(gate_kernel, cudaFuncAttributeMaxDynamicSharedMemorySize,
                             GATE_FL * 4);
        cudaFuncSetAttribute(head_kernel, cudaFuncAttributeMaxDynamicSharedMemorySize,
                             HEAD_FL * 4);
        configured = 1;
    }

    prep_kernel<<<418, 1024>>>(fc0, fc1, w, w1, y);
    gate_kernel<<<dim3(F / 64, BATCH / 128), 256, GATE_FL * 4>>>(x, y);
    head_kernel<<<BATCH / 128, 256, HEAD_FL * 4>>>(w1, y);
    final_kernel<<<1, 1024>>>(out);
}